// round 11
// baseline (speedup 1.0000x reference)
#include <cuda_runtime.h>
#include <cuda_fp16.h>
#include <math.h>
#include <stdint.h>

#define Bx 4
#define Lx 2048
#define Dx 512
#define Hx 8
#define DHx 64
#define BHx 32
#define KTOP 38
#define KHALF 19
#define SCALEF 0.125f
#define SH 72   // score smem halves per row
#define SW 36   // score smem words per row (36 % 32 == 4 -> conflict-free)
#define PSH 40  // proj stage halves per row
#define PSW 20  // proj stage words per row (20 % 32 -> full bank coverage)

// ---------------- scratch (device globals; no allocation allowed) ----------
__device__ float  g_Q[BHx * Lx * DHx];
__device__ float  g_K[BHx * Lx * DHx];
__device__ float  g_V[BHx * Lx * DHx];
__device__ __half g_Xhi[Bx * Lx * Dx];
__device__ __half g_Xlo[Bx * Lx * Dx];
__device__ __half g_WThi[3 * Dx * Dx];   // W^T, [c][k], per projection
__device__ __half g_WTlo[3 * Dx * Dx];
__device__ __half g_Qhi[BHx * Lx * DHx];
__device__ __half g_Qlo[BHx * Lx * DHx];
__device__ __half g_Khi[BHx * Lx * DHx];
__device__ __half g_Klo[BHx * Lx * DHx];
__device__ float  g_rowmax[BHx * Lx];
__device__ float  g_M[BHx * Lx];
__device__ int    g_top[BHx * KTOP];
__device__ float  g_Ksum[BHx * DHx];
__device__ float  g_Vsum[BHx * DHx];
__device__ float  g_delta[BHx * KTOP * DHx];
__device__ float  g_base[Bx * Dx];

// ---------------- helpers ----------------------------------------------------
__device__ __forceinline__ void mma_f16(float c[4], const uint32_t a[4],
                                        uint32_t b0, uint32_t b1) {
    asm volatile(
        "mma.sync.aligned.m16n8k16.row.col.f32.f16.f16.f32 "
        "{%0,%1,%2,%3}, {%4,%5,%6,%7}, {%8,%9}, {%0,%1,%2,%3};"
        : "+f"(c[0]), "+f"(c[1]), "+f"(c[2]), "+f"(c[3])
        : "r"(a[0]), "r"(a[1]), "r"(a[2]), "r"(a[3]), "r"(b0), "r"(b1));
}
__device__ __forceinline__ void split_h(float f, __half& h, __half& l) {
    h = __float2half_rn(f);
    l = __float2half_rn(f - __half2float(h));
}
__device__ __forceinline__ uint32_t smem_u32(const void* p) {
    uint32_t a;
    asm("{ .reg .u64 t; cvta.to.shared.u64 t, %1; cvt.u32.u64 %0, t; }"
        : "=r"(a) : "l"(p));
    return a;
}
__device__ __forceinline__ void cp16(uint32_t s, const void* g) {
    asm volatile("cp.async.cg.shared.global [%0], [%1], 16;" :: "r"(s), "l"(g));
}
#define CP_COMMIT() asm volatile("cp.async.commit_group;" ::: "memory")
#define CP_WAIT(N)  asm volatile("cp.async.wait_group %0;" :: "n"(N) : "memory")

// ---------------------------------------------------------------------------
// prep_w: transpose W[k][c] -> WT[c][k], split fp16 hi/lo. grid(16,16,3).
// ---------------------------------------------------------------------------
__global__ void prep_w_kernel(const float* __restrict__ Wq,
                              const float* __restrict__ Wk,
                              const float* __restrict__ Wv)
{
    __shared__ float s[32][33];
    const float* W = (blockIdx.z == 0) ? Wq : (blockIdx.z == 1) ? Wk : Wv;
    __half* dh = g_WThi + (size_t)blockIdx.z * Dx * Dx;
    __half* dl = g_WTlo + (size_t)blockIdx.z * Dx * Dx;
    const int kt = blockIdx.y * 32, ct = blockIdx.x * 32;
    const int tid = threadIdx.x;
    {
        int r = tid >> 3, c4 = (tid & 7) * 4;
        float4 v = *reinterpret_cast<const float4*>(&W[(size_t)(kt + r) * Dx + ct + c4]);
        s[r][c4] = v.x; s[r][c4 + 1] = v.y; s[r][c4 + 2] = v.z; s[r][c4 + 3] = v.w;
    }
    __syncthreads();
    {
        int cw = tid >> 3, k4 = (tid & 7) * 4;
        size_t o = (size_t)(ct + cw) * Dx + kt + k4;
#pragma unroll
        for (int j = 0; j < 4; j += 2) {
            __half h0, l0, h1, l1;
            split_h(s[k4 + j][cw], h0, l0);
            split_h(s[k4 + j + 1][cw], h1, l1);
            *reinterpret_cast<__half2*>(&dh[o + j]) = __halves2half2(h0, h1);
            *reinterpret_cast<__half2*>(&dl[o + j]) = __halves2half2(l0, l1);
        }
    }
}

// ---------------------------------------------------------------------------
// prep_x: split x to fp16 hi/lo.
// ---------------------------------------------------------------------------
__global__ void prep_x_kernel(const float* __restrict__ X)
{
    size_t i4 = (size_t)blockIdx.x * 256 + threadIdx.x;
    float4 v = *reinterpret_cast<const float4*>(X + i4 * 4);
    __half h0, l0, h1, l1, h2, l2, h3, l3;
    split_h(v.x, h0, l0); split_h(v.y, h1, l1);
    split_h(v.z, h2, l2); split_h(v.w, h3, l3);
    size_t o = i4 * 4;
    *reinterpret_cast<__half2*>(&g_Xhi[o])     = __halves2half2(h0, h1);
    *reinterpret_cast<__half2*>(&g_Xhi[o + 2]) = __halves2half2(h2, h3);
    *reinterpret_cast<__half2*>(&g_Xlo[o])     = __halves2half2(l0, l1);
    *reinterpret_cast<__half2*>(&g_Xlo[o + 2]) = __halves2half2(l2, l3);
}

// ---------------------------------------------------------------------------
// proj_mma: Y = X @ W + b; block tile 128m x 64n, BK=32, cp.async 2-stage.
// grid (8, 64, 3). 8 warps: wm = w>>1 (0..3), wn = w&1 (0..1).
// Warp tile 32m x 32n -> 8 C tiles -> ~32 C regs -> 2 CTAs/SM.
// ---------------------------------------------------------------------------
#define PROJ_STAGE ((2 * 128 + 2 * 64) * PSH)      // halves per stage (15360)
#define PROJ_SMEM  (2 * PROJ_STAGE * 2)            // bytes (61440)

__global__ __launch_bounds__(256, 2)
void proj_mma_kernel(const float* __restrict__ bq, const float* __restrict__ bk,
                     const float* __restrict__ bv)
{
    extern __shared__ __half smh[];
    const int tid = threadIdx.x;
    const int w = tid >> 5, lane = tid & 31;
    const int gr = lane >> 2, tc = lane & 3;
    const int wm = w >> 1, wn = w & 1;
    const int mbase = blockIdx.y * 128;
    const int nbase = blockIdx.x * 64;
    const int z = blockIdx.z;

    const __half* WTh = g_WThi + (size_t)z * Dx * Dx;
    const __half* WTl = g_WTlo + (size_t)z * Dx * Dx;
    const float* bias = (z == 0) ? bq : (z == 1) ? bk : bv;
    float* out = (z == 0) ? g_Q : (z == 1) ? g_K : g_V;
    __half* outHi = (z == 0) ? g_Qhi : (z == 1) ? g_Khi : (__half*)0;
    __half* outLo = (z == 0) ? g_Qlo : (z == 1) ? g_Klo : (__half*)0;

    const uint32_t sb0 = smem_u32(smh);

    // stage halves layout: Xh[128*PSH] | Xl[128*PSH] | Wh[64*PSH] | Wl[64*PSH]
    auto prefetch = [&](int kt_i, int stage) {
        const int kt = kt_i * 32;
        const uint32_t sb = sb0 + (uint32_t)(stage * PROJ_STAGE * 2);
#pragma unroll
        for (int i = 0; i < 6; i++) {
            int idx = tid + i * 256;          // 0..1535
            const __half* gp;
            uint32_t soff;
            if (idx < 512) {                  // Xh
                int r = idx >> 2, u = (idx & 3) * 8;
                soff = (uint32_t)(r * PSH + u);
                gp = g_Xhi + (size_t)(mbase + r) * Dx + kt + u;
            } else if (idx < 1024) {          // Xl
                int v = idx - 512;
                int r = v >> 2, u = (v & 3) * 8;
                soff = (uint32_t)(128 * PSH + r * PSH + u);
                gp = g_Xlo + (size_t)(mbase + r) * Dx + kt + u;
            } else if (idx < 1280) {          // Wh
                int v = idx - 1024;
                int r = v >> 2, u = (v & 3) * 8;
                soff = (uint32_t)(256 * PSH + r * PSH + u);
                gp = WTh + (size_t)(nbase + r) * Dx + kt + u;
            } else {                          // Wl
                int v = idx - 1280;
                int r = v >> 2, u = (v & 3) * 8;
                soff = (uint32_t)(256 * PSH + 64 * PSH + r * PSH + u);
                gp = WTl + (size_t)(nbase + r) * Dx + kt + u;
            }
            cp16(sb + soff * 2, gp);
        }
        CP_COMMIT();
    };

    float C[8][4];
#pragma unroll
    for (int p = 0; p < 8; p++)
#pragma unroll
        for (int j = 0; j < 4; j++) C[p][j] = 0.f;

    prefetch(0, 0);

    for (int it = 0; it < 16; it++) {
        const int stage = it & 1;
        if (it < 15) { prefetch(it + 1, stage ^ 1); CP_WAIT(1); }
        else         { CP_WAIT(0); }
        __syncthreads();

        const __half* Xh = smh + stage * PROJ_STAGE;
        const __half* Xl = Xh + 128 * PSH;
        const __half* Wh = Xl + 128 * PSH;
        const __half* Wl = Wh + 64 * PSH;

#pragma unroll
        for (int k16 = 0; k16 < 2; k16++) {
            const int kw = k16 * 8;
            uint32_t ah[2][4], al[2][4];
#pragma unroll
            for (int mi = 0; mi < 2; mi++) {
                int row = (wm * 2 + mi) * 16 + gr;
                const uint32_t* ph = reinterpret_cast<const uint32_t*>(Xh) + row * PSW + kw;
                const uint32_t* pl = reinterpret_cast<const uint32_t*>(Xl) + row * PSW + kw;
                ah[mi][0] = ph[tc];           ah[mi][1] = ph[8 * PSW + tc];
                ah[mi][2] = ph[tc + 4];       ah[mi][3] = ph[8 * PSW + tc + 4];
                al[mi][0] = pl[tc];           al[mi][1] = pl[8 * PSW + tc];
                al[mi][2] = pl[tc + 4];       al[mi][3] = pl[8 * PSW + tc + 4];
            }
#pragma unroll
            for (int ni = 0; ni < 4; ni++) {
                int key = (wn * 4 + ni) * 8 + gr;
                const uint32_t* qh = reinterpret_cast<const uint32_t*>(Wh) + key * PSW + kw;
                const uint32_t* ql = reinterpret_cast<const uint32_t*>(Wl) + key * PSW + kw;
                uint32_t bh0 = qh[tc], bh1 = qh[tc + 4];
                uint32_t bl0 = ql[tc], bl1 = ql[tc + 4];
#pragma unroll
                for (int mi = 0; mi < 2; mi++) {
                    mma_f16(C[mi * 4 + ni], ah[mi], bh0, bh1);
                    mma_f16(C[mi * 4 + ni], ah[mi], bl0, bl1);
                    mma_f16(C[mi * 4 + ni], al[mi], bh0, bh1);
                }
            }
        }
        __syncthreads();
    }

    // epilogue: [bh][l][d] layout, fp32 (+ fp16 hi/lo for Q, K)
#pragma unroll
    for (int mi = 0; mi < 2; mi++) {
#pragma unroll
        for (int ni = 0; ni < 4; ni++) {
            const float* c = C[mi * 4 + ni];
            int col = nbase + (wn * 4 + ni) * 8 + 2 * tc;
            int h = col >> 6, d = col & 63;
            float b0 = bias[col], b1 = bias[col + 1];
#pragma unroll
            for (int half_ = 0; half_ < 2; half_++) {
                int r = mbase + (wm * 2 + mi) * 16 + gr + half_ * 8;
                int bb = r >> 11, l = r & 2047;
                size_t o = (((size_t)(bb * Hx + h)) * Lx + l) * DHx + d;
                float v0 = c[half_ * 2] + b0;
                float v1 = c[half_ * 2 + 1] + b1;
                *reinterpret_cast<float2*>(&out[o]) = make_float2(v0, v1);
                if (outHi) {
                    __half h0, l0, h1, l1;
                    split_h(v0, h0, l0);
                    split_h(v1, h1, l1);
                    *reinterpret_cast<__half2*>(&outHi[o]) = __halves2half2(h0, h1);
                    *reinterpret_cast<__half2*>(&outLo[o]) = __halves2half2(l0, l1);
                }
            }
        }
    }
}

// ---------------------------------------------------------------------------
// score_mma: rowmax(Q[128,64] @ K^T). K streamed 64 keys/step, 32 steps,
// cp.async 2-stage. 8 warps: wm = w>>1, wn = w&1. 8 C tiles -> 2 CTAs/SM.
// ---------------------------------------------------------------------------
#define KSTAGE (2 * 64 * SH)    // halves per K stage
#define SCORE_SMEM ((2 * 128 * SH + 2 * KSTAGE) * 2 + 2 * 128 * 4)

__global__ __launch_bounds__(256, 2)
void score_mma_kernel()
{
    extern __shared__ __half smh[];
    __half* Qh = smh;
    __half* Ql = Qh + 128 * SH;
    __half* Kst = Ql + 128 * SH;             // 2 stages follow
    float* red = reinterpret_cast<float*>(Kst + 2 * KSTAGE);  // [2][128]

    const int tid = threadIdx.x;
    const int w = tid >> 5, lane = tid & 31;
    const int gr = lane >> 2, tc = lane & 3;
    const int wm = w >> 1, wn = w & 1;
    const int bh = blockIdx.y;
    const int qbase = blockIdx.x * 128;

    const uint32_t kst_u32 = smem_u32(Kst);

    auto prefetch_k = [&](int t, int stage) {
        const uint32_t sb = kst_u32 + (uint32_t)(stage * KSTAGE * 2);
#pragma unroll
        for (int i = 0; i < 4; i++) {
            int idx = tid + i * 256;         // 0..1023
            int buf = idx >> 9;              // 0 = hi, 1 = lo
            int within = idx & 511;
            int r = within >> 3;             // 0..63
            int u = (within & 7) * 8;
            uint32_t sa = sb + (uint32_t)((buf * 64 * SH + r * SH + u) * 2);
            const __half* gp = (buf == 0 ? g_Khi : g_Klo)
                               + ((size_t)bh * Lx + t * 64 + r) * DHx + u;
            cp16(sa, gp);
        }
        CP_COMMIT();
    };

    // Q fill once (regular loads)
#pragma unroll
    for (int i = 0; i < 4; i++) {
        int idx = tid + i * 256;
        int r = idx >> 3;
        int u = (idx & 7) * 8;
        size_t qs = ((size_t)bh * Lx + qbase + r) * DHx + u;
        *reinterpret_cast<uint4*>(Qh + r * SH + u) =
            *reinterpret_cast<const uint4*>(g_Qhi + qs);
        *reinterpret_cast<uint4*>(Ql + r * SH + u) =
            *reinterpret_cast<const uint4*>(g_Qlo + qs);
    }

    prefetch_k(0, 0);

    float rm0[2], rm1[2];
#pragma unroll
    for (int mi = 0; mi < 2; mi++) { rm0[mi] = -1e30f; rm1[mi] = -1e30f; }

    for (int t = 0; t < 32; t++) {
        const int stage = t & 1;
        if (t < 31) { prefetch_k(t + 1, stage ^ 1); CP_WAIT(1); }
        else        { CP_WAIT(0); }
        __syncthreads();

        const __half* Kh = Kst + stage * KSTAGE;
        const __half* Kl = Kh + 64 * SH;

        float C[8][4];
#pragma unroll
        for (int p = 0; p < 8; p++)
#pragma unroll
            for (int j = 0; j < 4; j++) C[p][j] = 0.f;

#pragma unroll
        for (int k16 = 0; k16 < 4; k16++) {
            const int kw = k16 * 8;
            uint32_t ah[2][4], al[2][4];
#pragma unroll
            for (int mi = 0; mi < 2; mi++) {
                int row = (wm * 2 + mi) * 16 + gr;
                const uint32_t* ph = reinterpret_cast<const uint32_t*>(Qh) + row * SW + kw;
                const uint32_t* pl = reinterpret_cast<const uint32_t*>(Ql) + row * SW + kw;
                ah[mi][0] = ph[tc];           ah[mi][1] = ph[8 * SW + tc];
                ah[mi][2] = ph[tc + 4];       ah[mi][3] = ph[8 * SW + tc + 4];
                al[mi][0] = pl[tc];           al[mi][1] = pl[8 * SW + tc];
                al[mi][2] = pl[tc + 4];       al[mi][3] = pl[8 * SW + tc + 4];
            }
#pragma unroll
            for (int ni = 0; ni < 4; ni++) {
                int key = (wn * 4 + ni) * 8 + gr;
                const uint32_t* qh = reinterpret_cast<const uint32_t*>(Kh) + key * SW + kw;
                const uint32_t* ql = reinterpret_cast<const uint32_t*>(Kl) + key * SW + kw;
                uint32_t bh0 = qh[tc], bh1 = qh[tc + 4];
                uint32_t bl0 = ql[tc], bl1 = ql[tc + 4];
#pragma unroll
                for (int mi = 0; mi < 2; mi++) {
                    mma_f16(C[mi * 4 + ni], ah[mi], bh0, bh1);
                    mma_f16(C[mi * 4 + ni], ah[mi], bl0, bl1);
                    mma_f16(C[mi * 4 + ni], al[mi], bh0, bh1);
                }
            }
        }

#pragma unroll
        for (int mi = 0; mi < 2; mi++)
#pragma unroll
            for (int ni = 0; ni < 4; ni++) {
                const float* c = C[mi * 4 + ni];
                rm0[mi] = fmaxf(rm0[mi], fmaxf(c[0], c[1]));
                rm1[mi] = fmaxf(rm1[mi], fmaxf(c[2], c[3]));
            }
        __syncthreads();
    }

#pragma unroll
    for (int mi = 0; mi < 2; mi++) {
        rm0[mi] = fmaxf(rm0[mi], __shfl_xor_sync(0xffffffffu, rm0[mi], 1));
        rm0[mi] = fmaxf(rm0[mi], __shfl_xor_sync(0xffffffffu, rm0[mi], 2));
        rm1[mi] = fmaxf(rm1[mi], __shfl_xor_sync(0xffffffffu, rm1[mi], 1));
        rm1[mi] = fmaxf(rm1[mi], __shfl_xor_sync(0xffffffffu, rm1[mi], 2));
    }
    if (tc == 0) {
#pragma unroll
        for (int mi = 0; mi < 2; mi++) {
            int row = (wm * 2 + mi) * 16 + gr;
            red[wn * 128 + row] = rm0[mi];
            red[wn * 128 + row + 8] = rm1[mi];
        }
    }
    __syncthreads();
    if (tid < 128) {
        float m = fmaxf(red[tid], red[128 + tid]);
        g_rowmax[(size_t)bh * Lx + qbase + tid] = m;
    }
}

// ---------------------------------------------------------------------------
// K / V column sums.
// ---------------------------------------------------------------------------
__global__ void zero_sums_kernel()
{
    int i = blockIdx.x * blockDim.x + threadIdx.x;
    if (i < BHx * DHx) { g_Ksum[i] = 0.f; g_Vsum[i] = 0.f; }
}

__global__ void partial_sums_kernel()
{
    const int bh = blockIdx.x;
    const int kb = blockIdx.y * 128;
    const int tid = threadIdx.x;
    const int d = tid & 63, s = tid >> 6;
    float ks = 0.f, vs = 0.f;
    for (int k = kb + s; k < kb + 128; k += 4) {
        ks += g_K[((size_t)bh * Lx + k) * DHx + d];
        vs += g_V[((size_t)bh * Lx + k) * DHx + d];
    }
    __shared__ float red[2][256];
    red[0][tid] = ks;
    red[1][tid] = vs;
    __syncthreads();
    if (tid < 64) {
        float a = red[0][d] + red[0][d + 64] + red[0][d + 128] + red[0][d + 192];
        float b = red[1][d] + red[1][d + 64] + red[1][d + 128] + red[1][d + 192];
        atomicAdd(&g_Ksum[bh * DHx + d], a);
        atomicAdd(&g_Vsum[bh * DHx + d], b);
    }
}

// ---------------------------------------------------------------------------
// M = SCALE * (rowmax - Q.Ksum / L)
// ---------------------------------------------------------------------------
__global__ void mstat_kernel()
{
    int gidx = blockIdx.x * 256 + threadIdx.x;
    int bh = gidx >> 11;
    const float* qp = g_Q + (size_t)gidx * DHx;
    const float* ks = g_Ksum + bh * DHx;
    float dot = 0.f;
#pragma unroll
    for (int d = 0; d < DHx; d += 4) {
        float4 a = *reinterpret_cast<const float4*>(qp + d);
        float4 b = *reinterpret_cast<const float4*>(ks + d);
        dot += a.x * b.x + a.y * b.y + a.z * b.z + a.w * b.w;
    }
    g_M[gidx] = SCALEF * (g_rowmax[gidx] - dot * (1.0f / Lx));
}

// ---------------------------------------------------------------------------
// Top-38 selection per bh.
// ---------------------------------------------------------------------------
__global__ void topk_kernel()
{
    int bh = blockIdx.x;
    int tid = threadIdx.x;
    __shared__ float vals[Lx];
    __shared__ float rv[256];
    __shared__ int ri[256];
    for (int i = tid; i < Lx; i += 256) vals[i] = g_M[(size_t)bh * Lx + i];
    __syncthreads();
    for (int it = 0; it < KTOP; it++) {
        float best = -1e30f;
        int bidx = 0;
        for (int i = tid; i < Lx; i += 256) {
            float v = vals[i];
            if (v > best) { best = v; bidx = i; }
        }
        rv[tid] = best;
        ri[tid] = bidx;
        __syncthreads();
        for (int s = 128; s > 0; s >>= 1) {
            if (tid < s) {
                if (rv[tid + s] > rv[tid] ||
                    (rv[tid + s] == rv[tid] && ri[tid + s] < ri[tid])) {
                    rv[tid] = rv[tid + s];
                    ri[tid] = ri[tid + s];
                }
            }
            __syncthreads();
        }
        if (tid == 0) {
            g_top[bh * KTOP + it] = ri[0];
            vals[ri[0]] = -1e30f;
        }
        __syncthreads();
    }
}

// ---------------------------------------------------------------------------
// Sparse attention, 2 queries per block (exact fp32).
// ---------------------------------------------------------------------------
__global__ __launch_bounds__(256)
void sparse_attn_kernel()
{
    const int bh = blockIdx.y;
    const int i0 = blockIdx.x;
    const int i1 = blockIdx.x + KHALF;
    const int tid = threadIdx.x;
    const int q0 = g_top[bh * KTOP + i0];
    const int q1 = g_top[bh * KTOP + i1];

    __shared__ float sc0[Lx];
    __shared__ float sc1[Lx];
    __shared__ float qrow[2][DHx];
    __shared__ float red[256];

    if (tid < 64) {
        qrow[0][tid] = g_Q[((size_t)bh * Lx + q0) * DHx + tid];
        qrow[1][tid] = g_Q[((size_t)bh * Lx + q1) * DHx + tid];
    }
    __syncthreads();

    const int warp = tid >> 5, lane = tid & 31;
    const float qa0 = qrow[0][lane], qa1 = qrow[0][lane + 32];
    const float qb0 = qrow[1][lane], qb1 = qrow[1][lane + 32];
    for (int k = warp; k < Lx; k += 8) {
        const float* kr = g_K + ((size_t)bh * Lx + k) * DHx;
        float k0 = kr[lane], k1 = kr[lane + 32];
        float pa = k0 * qa0 + k1 * qa1;
        float pb = k0 * qb0 + k1 * qb1;
#pragma unroll
        for (int o = 16; o > 0; o >>= 1) {
            pa += __shfl_xor_sync(0xffffffffu, pa, o);
            pb += __shfl_xor_sync(0xffffffffu, pb, o);
        }
        if (lane == 0) { sc0[k] = pa * SCALEF; sc1[k] = pb * SCALEF; }
    }
    __syncthreads();

    float inv0, inv1;
    for (int qq = 0; qq < 2; qq++) {
        float* sc = qq ? sc1 : sc0;
        float mx = -1e30f;
        for (int k = tid; k < Lx; k += 256) mx = fmaxf(mx, sc[k]);
        red[tid] = mx;
        __syncthreads();
        for (int s = 128; s > 0; s >>= 1) {
            if (tid < s) red[tid] = fmaxf(red[tid], red[tid + s]);
            __syncthreads();
        }
        mx = red[0];
        __syncthreads();
        float sum = 0.f;
        for (int k = tid; k < Lx; k += 256) {
            float e = __expf(sc[k] - mx);
            sc[k] = e;
            sum += e;
        }
        red[tid] = sum;
        __syncthreads();
        for (int s = 128; s > 0; s >>= 1) {
            if (tid < s) red[tid] += red[tid + s];
            __syncthreads();
        }
        if (qq == 0) inv0 = 1.0f / red[0]; else inv1 = 1.0f / red[0];
        __syncthreads();
    }

    const int d = tid & 63, s4 = tid >> 6;
    float acc0 = 0.f, acc1 = 0.f;
    for (int k = s4; k < Lx; k += 4) {
        float v = g_V[((size_t)bh * Lx + k) * DHx + d];
        acc0 += sc0[k] * v;
        acc1 += sc1[k] * v;
    }
    __shared__ float red2[2][256];
    red2[0][tid] = acc0;
    red2[1][tid] = acc1;
    __syncthreads();
    if (tid < 64) {
        float vm = g_Vsum[bh * DHx + d] * (1.0f / Lx);
        float c0 = (red2[0][d] + red2[0][d + 64] + red2[0][d + 128] + red2[0][d + 192]) * inv0;
        float c1 = (red2[1][d] + red2[1][d + 64] + red2[1][d + 128] + red2[1][d + 192]) * inv1;
        g_delta[((size_t)bh * KTOP + i0) * DHx + d] = c0 - vm;
        g_delta[((size_t)bh * KTOP + i1) * DHx + d] = c1 - vm;
    }
}

// ---------------------------------------------------------------------------
__global__ void base_kernel(const float* __restrict__ Wo, const float* __restrict__ bo)
{
    int b = blockIdx.x, j = threadIdx.x;
    float acc = bo[j];
    for (int c = 0; c < Dx; c++) {
        int h = c >> 6, d = c & 63;
        acc += g_Vsum[(b * Hx + h) * DHx + d] * (1.0f / Lx) * Wo[(size_t)c * Dx + j];
    }
    g_base[b * Dx + j] = acc;
}

__global__ void fill_kernel(float* __restrict__ out)
{
    size_t idx = (size_t)blockIdx.x * blockDim.x + threadIdx.x;
    if (idx < (size_t)Bx * Lx * Dx) {
        int b = (int)(idx / ((size_t)Lx * Dx));
        int j = (int)(idx % Dx);
        out[idx] = g_base[b * Dx + j];
    }
}

__global__ void scatter_kernel(const float* __restrict__ Wo, float* __restrict__ out)
{
    const int bh = blockIdx.y;
    const int i = blockIdx.x;
    const int j = threadIdx.x;  // 512
    const int b = bh >> 3, h = bh & 7;
    const int l = g_top[bh * KTOP + i];
    __shared__ float dl[DHx];
    if (j < 64) dl[j] = g_delta[((size_t)bh * KTOP + i) * DHx + j];
    __syncthreads();
    float acc = 0.f;
#pragma unroll 16
    for (int d = 0; d < 64; d++) acc += dl[d] * Wo[(size_t)(h * 64 + d) * Dx + j];
    atomicAdd(&out[((size_t)b * Lx + l) * Dx + j], acc);
}

// ---------------------------------------------------------------------------
extern "C" void kernel_launch(void* const* d_in, const int* in_sizes, int n_in,
                              void* d_out, int out_size)
{
    const float* x  = (const float*)d_in[0];
    const float* Wq = (const float*)d_in[1];
    const float* bq = (const float*)d_in[2];
    const float* Wk = (const float*)d_in[3];
    const float* bk = (const float*)d_in[4];
    const float* Wv = (const float*)d_in[5];
    const float* bv = (const float*)d_in[6];
    const float* Wo = (const float*)d_in[7];
    const float* bo = (const float*)d_in[8];
    float* out = (float*)d_out;

    (void)in_sizes; (void)n_in; (void)out_size;

    cudaFuncSetAttribute(proj_mma_kernel,
                         cudaFuncAttributeMaxDynamicSharedMemorySize, PROJ_SMEM);
    cudaFuncSetAttribute(score_mma_kernel,
                         cudaFuncAttributeMaxDynamicSharedMemorySize, SCORE_SMEM);

    prep_w_kernel<<<dim3(16, 16, 3), 256>>>(Wq, Wk, Wv);          // 0
    prep_x_kernel<<<(Bx * Lx * Dx / 4) / 256, 256>>>(x);          // 1

    dim3 pg(Dx / 64, (Bx * Lx) / 128, 3);   // (8, 64, 3)
    proj_mma_kernel<<<pg, 256, PROJ_SMEM>>>(bq, bk, bv);          // 2

    zero_sums_kernel<<<(BHx * DHx + 255) / 256, 256>>>();         // 3
    partial_sums_kernel<<<dim3(BHx, 16), 256>>>();                // 4

    score_mma_kernel<<<dim3(Lx / 128, BHx), 256, SCORE_SMEM>>>(); // 5

    mstat_kernel<<<BHx * Lx / 256, 256>>>();

    topk_kernel<<<BHx, 256>>>();

    sparse_attn_kernel<<<dim3(KHALF, BHx), 256>>>();

    base_kernel<<<Bx, Dx>>>(Wo, bo);
    fill_kernel<<<(Bx * Lx * Dx + 255) / 256, 256>>>(out);
    scatter_kernel<<<dim3(KTOP, BHx), Dx>>>(Wo, out);
}

// round 12
// speedup vs baseline: 1.3937x; 1.3937x over previous
#include <cuda_runtime.h>
#include <cuda_fp16.h>
#include <math.h>
#include <stdint.h>

#define Bx 4
#define Lx 2048
#define Dx 512
#define Hx 8
#define DHx 64
#define BHx 32
#define KTOP 38
#define NQB 10        // sparse_attn blocks per bh (4 queries each, 40 slots)
#define SCALEF 0.125f
#define SH 72   // score smem halves per row
#define SW 36   // score smem words per row (36 % 32 == 4 -> conflict-free)
#define PSH 40  // proj stage halves per row
#define PSW 20  // proj stage words per row

// ---------------- scratch (device globals; no allocation allowed) ----------
__device__ float  g_Q[BHx * Lx * DHx];
__device__ float  g_K[BHx * Lx * DHx];
__device__ float  g_V[BHx * Lx * DHx];
__device__ __half g_Xhi[Bx * Lx * Dx];
__device__ __half g_Xlo[Bx * Lx * Dx];
__device__ __half g_WThi[3 * Dx * Dx];
__device__ __half g_WTlo[3 * Dx * Dx];
__device__ __half g_Qhi[BHx * Lx * DHx];
__device__ __half g_Qlo[BHx * Lx * DHx];
__device__ __half g_Khi[BHx * Lx * DHx];
__device__ __half g_Klo[BHx * Lx * DHx];
__device__ float  g_rowmax[BHx * Lx];
__device__ float  g_M[BHx * Lx];
__device__ int    g_top[BHx * KTOP];
__device__ float  g_Ksum[BHx * DHx];
__device__ float  g_Vsum[BHx * DHx];
__device__ float  g_delta[BHx * KTOP * DHx];
__device__ float  g_base[Bx * Dx];

// ---------------- helpers ----------------------------------------------------
__device__ __forceinline__ void mma_f16(float c[4], const uint32_t a[4],
                                        uint32_t b0, uint32_t b1) {
    asm volatile(
        "mma.sync.aligned.m16n8k16.row.col.f32.f16.f16.f32 "
        "{%0,%1,%2,%3}, {%4,%5,%6,%7}, {%8,%9}, {%0,%1,%2,%3};"
        : "+f"(c[0]), "+f"(c[1]), "+f"(c[2]), "+f"(c[3])
        : "r"(a[0]), "r"(a[1]), "r"(a[2]), "r"(a[3]), "r"(b0), "r"(b1));
}
__device__ __forceinline__ void split_h(float f, __half& h, __half& l) {
    h = __float2half_rn(f);
    l = __float2half_rn(f - __half2float(h));
}
__device__ __forceinline__ uint32_t smem_u32(const void* p) {
    uint32_t a;
    asm("{ .reg .u64 t; cvta.to.shared.u64 t, %1; cvt.u32.u64 %0, t; }"
        : "=r"(a) : "l"(p));
    return a;
}
__device__ __forceinline__ void cp16(uint32_t s, const void* g) {
    asm volatile("cp.async.cg.shared.global [%0], [%1], 16;" :: "r"(s), "l"(g));
}
#define CP_COMMIT() asm volatile("cp.async.commit_group;" ::: "memory")
#define CP_WAIT(N)  asm volatile("cp.async.wait_group %0;" :: "n"(N) : "memory")

// ---------------------------------------------------------------------------
// prep_w: transpose W[k][c] -> WT[c][k], split fp16 hi/lo. grid(16,16,3).
// ---------------------------------------------------------------------------
__global__ void prep_w_kernel(const float* __restrict__ Wq,
                              const float* __restrict__ Wk,
                              const float* __restrict__ Wv)
{
    __shared__ float s[32][33];
    const float* W = (blockIdx.z == 0) ? Wq : (blockIdx.z == 1) ? Wk : Wv;
    __half* dh = g_WThi + (size_t)blockIdx.z * Dx * Dx;
    __half* dl = g_WTlo + (size_t)blockIdx.z * Dx * Dx;
    const int kt = blockIdx.y * 32, ct = blockIdx.x * 32;
    const int tid = threadIdx.x;
    {
        int r = tid >> 3, c4 = (tid & 7) * 4;
        float4 v = *reinterpret_cast<const float4*>(&W[(size_t)(kt + r) * Dx + ct + c4]);
        s[r][c4] = v.x; s[r][c4 + 1] = v.y; s[r][c4 + 2] = v.z; s[r][c4 + 3] = v.w;
    }
    __syncthreads();
    {
        int cw = tid >> 3, k4 = (tid & 7) * 4;
        size_t o = (size_t)(ct + cw) * Dx + kt + k4;
#pragma unroll
        for (int j = 0; j < 4; j += 2) {
            __half h0, l0, h1, l1;
            split_h(s[k4 + j][cw], h0, l0);
            split_h(s[k4 + j + 1][cw], h1, l1);
            *reinterpret_cast<__half2*>(&dh[o + j]) = __halves2half2(h0, h1);
            *reinterpret_cast<__half2*>(&dl[o + j]) = __halves2half2(l0, l1);
        }
    }
}

// ---------------------------------------------------------------------------
// prep_x: split x to fp16 hi/lo.
// ---------------------------------------------------------------------------
__global__ void prep_x_kernel(const float* __restrict__ X)
{
    size_t i4 = (size_t)blockIdx.x * 256 + threadIdx.x;
    float4 v = *reinterpret_cast<const float4*>(X + i4 * 4);
    __half h0, l0, h1, l1, h2, l2, h3, l3;
    split_h(v.x, h0, l0); split_h(v.y, h1, l1);
    split_h(v.z, h2, l2); split_h(v.w, h3, l3);
    size_t o = i4 * 4;
    *reinterpret_cast<__half2*>(&g_Xhi[o])     = __halves2half2(h0, h1);
    *reinterpret_cast<__half2*>(&g_Xhi[o + 2]) = __halves2half2(h2, h3);
    *reinterpret_cast<__half2*>(&g_Xlo[o])     = __halves2half2(l0, l1);
    *reinterpret_cast<__half2*>(&g_Xlo[o + 2]) = __halves2half2(l2, l3);
}

// ---------------------------------------------------------------------------
// proj_mma: Y = X @ W + b; block tile 128m x 64n, BK=32, cp.async 2-stage.
// ---------------------------------------------------------------------------
#define PROJ_STAGE ((2 * 128 + 2 * 64) * PSH)
#define PROJ_SMEM  (2 * PROJ_STAGE * 2)

__global__ __launch_bounds__(256, 2)
void proj_mma_kernel(const float* __restrict__ bq, const float* __restrict__ bk,
                     const float* __restrict__ bv)
{
    extern __shared__ __half smh[];
    const int tid = threadIdx.x;
    const int w = tid >> 5, lane = tid & 31;
    const int gr = lane >> 2, tc = lane & 3;
    const int wm = w >> 1, wn = w & 1;
    const int mbase = blockIdx.y * 128;
    const int nbase = blockIdx.x * 64;
    const int z = blockIdx.z;

    const __half* WTh = g_WThi + (size_t)z * Dx * Dx;
    const __half* WTl = g_WTlo + (size_t)z * Dx * Dx;
    const float* bias = (z == 0) ? bq : (z == 1) ? bk : bv;
    float* out = (z == 0) ? g_Q : (z == 1) ? g_K : g_V;
    __half* outHi = (z == 0) ? g_Qhi : (z == 1) ? g_Khi : (__half*)0;
    __half* outLo = (z == 0) ? g_Qlo : (z == 1) ? g_Klo : (__half*)0;

    const uint32_t sb0 = smem_u32(smh);

    auto prefetch = [&](int kt_i, int stage) {
        const int kt = kt_i * 32;
        const uint32_t sb = sb0 + (uint32_t)(stage * PROJ_STAGE * 2);
#pragma unroll
        for (int i = 0; i < 6; i++) {
            int idx = tid + i * 256;
            const __half* gp;
            uint32_t soff;
            if (idx < 512) {
                int r = idx >> 2, u = (idx & 3) * 8;
                soff = (uint32_t)(r * PSH + u);
                gp = g_Xhi + (size_t)(mbase + r) * Dx + kt + u;
            } else if (idx < 1024) {
                int v = idx - 512;
                int r = v >> 2, u = (v & 3) * 8;
                soff = (uint32_t)(128 * PSH + r * PSH + u);
                gp = g_Xlo + (size_t)(mbase + r) * Dx + kt + u;
            } else if (idx < 1280) {
                int v = idx - 1024;
                int r = v >> 2, u = (v & 3) * 8;
                soff = (uint32_t)(256 * PSH + r * PSH + u);
                gp = WTh + (size_t)(nbase + r) * Dx + kt + u;
            } else {
                int v = idx - 1280;
                int r = v >> 2, u = (v & 3) * 8;
                soff = (uint32_t)(256 * PSH + 64 * PSH + r * PSH + u);
                gp = WTl + (size_t)(nbase + r) * Dx + kt + u;
            }
            cp16(sb + soff * 2, gp);
        }
        CP_COMMIT();
    };

    float C[8][4];
#pragma unroll
    for (int p = 0; p < 8; p++)
#pragma unroll
        for (int j = 0; j < 4; j++) C[p][j] = 0.f;

    prefetch(0, 0);

    for (int it = 0; it < 16; it++) {
        const int stage = it & 1;
        if (it < 15) { prefetch(it + 1, stage ^ 1); CP_WAIT(1); }
        else         { CP_WAIT(0); }
        __syncthreads();

        const __half* Xh = smh + stage * PROJ_STAGE;
        const __half* Xl = Xh + 128 * PSH;
        const __half* Wh = Xl + 128 * PSH;
        const __half* Wl = Wh + 64 * PSH;

#pragma unroll
        for (int k16 = 0; k16 < 2; k16++) {
            const int kw = k16 * 8;
            uint32_t ah[2][4], al[2][4];
#pragma unroll
            for (int mi = 0; mi < 2; mi++) {
                int row = (wm * 2 + mi) * 16 + gr;
                const uint32_t* ph = reinterpret_cast<const uint32_t*>(Xh) + row * PSW + kw;
                const uint32_t* pl = reinterpret_cast<const uint32_t*>(Xl) + row * PSW + kw;
                ah[mi][0] = ph[tc];           ah[mi][1] = ph[8 * PSW + tc];
                ah[mi][2] = ph[tc + 4];       ah[mi][3] = ph[8 * PSW + tc + 4];
                al[mi][0] = pl[tc];           al[mi][1] = pl[8 * PSW + tc];
                al[mi][2] = pl[tc + 4];       al[mi][3] = pl[8 * PSW + tc + 4];
            }
#pragma unroll
            for (int ni = 0; ni < 4; ni++) {
                int key = (wn * 4 + ni) * 8 + gr;
                const uint32_t* qh = reinterpret_cast<const uint32_t*>(Wh) + key * PSW + kw;
                const uint32_t* ql = reinterpret_cast<const uint32_t*>(Wl) + key * PSW + kw;
                uint32_t bh0 = qh[tc], bh1 = qh[tc + 4];
                uint32_t bl0 = ql[tc], bl1 = ql[tc + 4];
#pragma unroll
                for (int mi = 0; mi < 2; mi++) {
                    mma_f16(C[mi * 4 + ni], ah[mi], bh0, bh1);
                    mma_f16(C[mi * 4 + ni], ah[mi], bl0, bl1);
                    mma_f16(C[mi * 4 + ni], al[mi], bh0, bh1);
                }
            }
        }
        __syncthreads();
    }

#pragma unroll
    for (int mi = 0; mi < 2; mi++) {
#pragma unroll
        for (int ni = 0; ni < 4; ni++) {
            const float* c = C[mi * 4 + ni];
            int col = nbase + (wn * 4 + ni) * 8 + 2 * tc;
            int h = col >> 6, d = col & 63;
            float b0 = bias[col], b1 = bias[col + 1];
#pragma unroll
            for (int half_ = 0; half_ < 2; half_++) {
                int r = mbase + (wm * 2 + mi) * 16 + gr + half_ * 8;
                int bb = r >> 11, l = r & 2047;
                size_t o = (((size_t)(bb * Hx + h)) * Lx + l) * DHx + d;
                float v0 = c[half_ * 2] + b0;
                float v1 = c[half_ * 2 + 1] + b1;
                *reinterpret_cast<float2*>(&out[o]) = make_float2(v0, v1);
                if (outHi) {
                    __half h0, l0, h1, l1;
                    split_h(v0, h0, l0);
                    split_h(v1, h1, l1);
                    *reinterpret_cast<__half2*>(&outHi[o]) = __halves2half2(h0, h1);
                    *reinterpret_cast<__half2*>(&outLo[o]) = __halves2half2(l0, l1);
                }
            }
        }
    }
}

// ---------------------------------------------------------------------------
// score_mma: rowmax(Q[128,64] @ K^T). K streamed 64 keys/step, cp.async 2-stage.
// ---------------------------------------------------------------------------
#define KSTAGE (2 * 64 * SH)
#define SCORE_SMEM ((2 * 128 * SH + 2 * KSTAGE) * 2 + 2 * 128 * 4)

__global__ __launch_bounds__(256, 2)
void score_mma_kernel()
{
    extern __shared__ __half smh[];
    __half* Qh = smh;
    __half* Ql = Qh + 128 * SH;
    __half* Kst = Ql + 128 * SH;
    float* red = reinterpret_cast<float*>(Kst + 2 * KSTAGE);

    const int tid = threadIdx.x;
    const int w = tid >> 5, lane = tid & 31;
    const int gr = lane >> 2, tc = lane & 3;
    const int wm = w >> 1, wn = w & 1;
    const int bh = blockIdx.y;
    const int qbase = blockIdx.x * 128;

    const uint32_t kst_u32 = smem_u32(Kst);

    auto prefetch_k = [&](int t, int stage) {
        const uint32_t sb = kst_u32 + (uint32_t)(stage * KSTAGE * 2);
#pragma unroll
        for (int i = 0; i < 4; i++) {
            int idx = tid + i * 256;
            int buf = idx >> 9;
            int within = idx & 511;
            int r = within >> 3;
            int u = (within & 7) * 8;
            uint32_t sa = sb + (uint32_t)((buf * 64 * SH + r * SH + u) * 2);
            const __half* gp = (buf == 0 ? g_Khi : g_Klo)
                               + ((size_t)bh * Lx + t * 64 + r) * DHx + u;
            cp16(sa, gp);
        }
        CP_COMMIT();
    };

#pragma unroll
    for (int i = 0; i < 4; i++) {
        int idx = tid + i * 256;
        int r = idx >> 3;
        int u = (idx & 7) * 8;
        size_t qs = ((size_t)bh * Lx + qbase + r) * DHx + u;
        *reinterpret_cast<uint4*>(Qh + r * SH + u) =
            *reinterpret_cast<const uint4*>(g_Qhi + qs);
        *reinterpret_cast<uint4*>(Ql + r * SH + u) =
            *reinterpret_cast<const uint4*>(g_Qlo + qs);
    }

    prefetch_k(0, 0);

    float rm0[2], rm1[2];
#pragma unroll
    for (int mi = 0; mi < 2; mi++) { rm0[mi] = -1e30f; rm1[mi] = -1e30f; }

    for (int t = 0; t < 32; t++) {
        const int stage = t & 1;
        if (t < 31) { prefetch_k(t + 1, stage ^ 1); CP_WAIT(1); }
        else        { CP_WAIT(0); }
        __syncthreads();

        const __half* Kh = Kst + stage * KSTAGE;
        const __half* Kl = Kh + 64 * SH;

        float C[8][4];
#pragma unroll
        for (int p = 0; p < 8; p++)
#pragma unroll
            for (int j = 0; j < 4; j++) C[p][j] = 0.f;

#pragma unroll
        for (int k16 = 0; k16 < 4; k16++) {
            const int kw = k16 * 8;
            uint32_t ah[2][4], al[2][4];
#pragma unroll
            for (int mi = 0; mi < 2; mi++) {
                int row = (wm * 2 + mi) * 16 + gr;
                const uint32_t* ph = reinterpret_cast<const uint32_t*>(Qh) + row * SW + kw;
                const uint32_t* pl = reinterpret_cast<const uint32_t*>(Ql) + row * SW + kw;
                ah[mi][0] = ph[tc];           ah[mi][1] = ph[8 * SW + tc];
                ah[mi][2] = ph[tc + 4];       ah[mi][3] = ph[8 * SW + tc + 4];
                al[mi][0] = pl[tc];           al[mi][1] = pl[8 * SW + tc];
                al[mi][2] = pl[tc + 4];       al[mi][3] = pl[8 * SW + tc + 4];
            }
#pragma unroll
            for (int ni = 0; ni < 4; ni++) {
                int key = (wn * 4 + ni) * 8 + gr;
                const uint32_t* qh = reinterpret_cast<const uint32_t*>(Kh) + key * SW + kw;
                const uint32_t* ql = reinterpret_cast<const uint32_t*>(Kl) + key * SW + kw;
                uint32_t bh0 = qh[tc], bh1 = qh[tc + 4];
                uint32_t bl0 = ql[tc], bl1 = ql[tc + 4];
#pragma unroll
                for (int mi = 0; mi < 2; mi++) {
                    mma_f16(C[mi * 4 + ni], ah[mi], bh0, bh1);
                    mma_f16(C[mi * 4 + ni], ah[mi], bl0, bl1);
                    mma_f16(C[mi * 4 + ni], al[mi], bh0, bh1);
                }
            }
        }

#pragma unroll
        for (int mi = 0; mi < 2; mi++)
#pragma unroll
            for (int ni = 0; ni < 4; ni++) {
                const float* c = C[mi * 4 + ni];
                rm0[mi] = fmaxf(rm0[mi], fmaxf(c[0], c[1]));
                rm1[mi] = fmaxf(rm1[mi], fmaxf(c[2], c[3]));
            }
        __syncthreads();
    }

#pragma unroll
    for (int mi = 0; mi < 2; mi++) {
        rm0[mi] = fmaxf(rm0[mi], __shfl_xor_sync(0xffffffffu, rm0[mi], 1));
        rm0[mi] = fmaxf(rm0[mi], __shfl_xor_sync(0xffffffffu, rm0[mi], 2));
        rm1[mi] = fmaxf(rm1[mi], __shfl_xor_sync(0xffffffffu, rm1[mi], 1));
        rm1[mi] = fmaxf(rm1[mi], __shfl_xor_sync(0xffffffffu, rm1[mi], 2));
    }
    if (tc == 0) {
#pragma unroll
        for (int mi = 0; mi < 2; mi++) {
            int row = (wm * 2 + mi) * 16 + gr;
            red[wn * 128 + row] = rm0[mi];
            red[wn * 128 + row + 8] = rm1[mi];
        }
    }
    __syncthreads();
    if (tid < 128) {
        float m = fmaxf(red[tid], red[128 + tid]);
        g_rowmax[(size_t)bh * Lx + qbase + tid] = m;
    }
}

// ---------------------------------------------------------------------------
// K / V column sums.
// ---------------------------------------------------------------------------
__global__ void zero_sums_kernel()
{
    int i = blockIdx.x * blockDim.x + threadIdx.x;
    if (i < BHx * DHx) { g_Ksum[i] = 0.f; g_Vsum[i] = 0.f; }
}

__global__ void partial_sums_kernel()
{
    const int bh = blockIdx.x;
    const int kb = blockIdx.y * 128;
    const int tid = threadIdx.x;
    const int d = tid & 63, s = tid >> 6;
    float ks = 0.f, vs = 0.f;
    for (int k = kb + s; k < kb + 128; k += 4) {
        ks += g_K[((size_t)bh * Lx + k) * DHx + d];
        vs += g_V[((size_t)bh * Lx + k) * DHx + d];
    }
    __shared__ float red[2][256];
    red[0][tid] = ks;
    red[1][tid] = vs;
    __syncthreads();
    if (tid < 64) {
        float a = red[0][d] + red[0][d + 64] + red[0][d + 128] + red[0][d + 192];
        float b = red[1][d] + red[1][d + 64] + red[1][d + 128] + red[1][d + 192];
        atomicAdd(&g_Ksum[bh * DHx + d], a);
        atomicAdd(&g_Vsum[bh * DHx + d], b);
    }
}

// ---------------------------------------------------------------------------
// M = SCALE * (rowmax - Q.Ksum / L)
// ---------------------------------------------------------------------------
__global__ void mstat_kernel()
{
    int gidx = blockIdx.x * 256 + threadIdx.x;
    int bh = gidx >> 11;
    const float* qp = g_Q + (size_t)gidx * DHx;
    const float* ks = g_Ksum + bh * DHx;
    float dot = 0.f;
#pragma unroll
    for (int d = 0; d < DHx; d += 4) {
        float4 a = *reinterpret_cast<const float4*>(qp + d);
        float4 b = *reinterpret_cast<const float4*>(ks + d);
        dot += a.x * b.x + a.y * b.y + a.z * b.z + a.w * b.w;
    }
    g_M[gidx] = SCALEF * (g_rowmax[gidx] - dot * (1.0f / Lx));
}

// ---------------------------------------------------------------------------
// Top-38 selection per bh.
// ---------------------------------------------------------------------------
__global__ void topk_kernel()
{
    int bh = blockIdx.x;
    int tid = threadIdx.x;
    __shared__ float vals[Lx];
    __shared__ float rv[256];
    __shared__ int ri[256];
    for (int i = tid; i < Lx; i += 256) vals[i] = g_M[(size_t)bh * Lx + i];
    __syncthreads();
    for (int it = 0; it < KTOP; it++) {
        float best = -1e30f;
        int bidx = 0;
        for (int i = tid; i < Lx; i += 256) {
            float v = vals[i];
            if (v > best) { best = v; bidx = i; }
        }
        rv[tid] = best;
        ri[tid] = bidx;
        __syncthreads();
        for (int s = 128; s > 0; s >>= 1) {
            if (tid < s) {
                if (rv[tid + s] > rv[tid] ||
                    (rv[tid + s] == rv[tid] && ri[tid + s] < ri[tid])) {
                    rv[tid] = rv[tid + s];
                    ri[tid] = ri[tid + s];
                }
            }
            __syncthreads();
        }
        if (tid == 0) {
            g_top[bh * KTOP + it] = ri[0];
            vals[ri[0]] = -1e30f;
        }
        __syncthreads();
    }
}

// ---------------------------------------------------------------------------
// Sparse attention, 4 queries per block, quarter-warp QK (exact fp32).
// grid (NQB, BHx); block handles queries i_s = blockIdx.x + NQB*s, s<4,
// valid if i_s < KTOP.
// ---------------------------------------------------------------------------
__global__ __launch_bounds__(256)
void sparse_attn_kernel()
{
    const int bh = blockIdx.y;
    const int tid = threadIdx.x;
    const int warp = tid >> 5, lane = tid & 31;
    const int qq = lane >> 3;       // quarter index 0..3
    const int l8 = lane & 7;        // lane within quarter

    __shared__ float sc[4][Lx];     // 32 KB
    __shared__ float qrow[4][DHx];  // 1 KB
    __shared__ float red[256];
    __shared__ float red2[4][256];  // 4 KB

    int qidx[4];
    bool valid[4];
#pragma unroll
    for (int s = 0; s < 4; s++) {
        int i = blockIdx.x + NQB * s;
        valid[s] = (i < KTOP);
        qidx[s] = valid[s] ? g_top[bh * KTOP + i] : 0;
    }

    // load 4 query rows (zero for invalid -> harmless scores)
    if (tid < 256) {
        int s = tid >> 6, d = tid & 63;
        qrow[s][d] = valid[s] ? g_Q[((size_t)bh * Lx + qidx[s]) * DHx + d] : 0.f;
    }
    __syncthreads();

    // preload q fragments: this lane's 8 dims for each query
    float4 qf[4][2];
#pragma unroll
    for (int s = 0; s < 4; s++) {
        qf[s][0] = *reinterpret_cast<const float4*>(&qrow[s][l8 * 8]);
        qf[s][1] = *reinterpret_cast<const float4*>(&qrow[s][l8 * 8 + 4]);
    }

    // QK: warp handles 4 consecutive keys per iteration (one per quarter)
    for (int it = 0; it < Lx / 32; it++) {
        int k = it * 32 + warp * 4 + qq;
        const float* kr = g_K + ((size_t)bh * Lx + k) * DHx;
        float4 a = *reinterpret_cast<const float4*>(kr + l8 * 8);
        float4 b = *reinterpret_cast<const float4*>(kr + l8 * 8 + 4);
        float d0, d1, d2, d3;
        {
            d0 = a.x*qf[0][0].x + a.y*qf[0][0].y + a.z*qf[0][0].z + a.w*qf[0][0].w
               + b.x*qf[0][1].x + b.y*qf[0][1].y + b.z*qf[0][1].z + b.w*qf[0][1].w;
            d1 = a.x*qf[1][0].x + a.y*qf[1][0].y + a.z*qf[1][0].z + a.w*qf[1][0].w
               + b.x*qf[1][1].x + b.y*qf[1][1].y + b.z*qf[1][1].z + b.w*qf[1][1].w;
            d2 = a.x*qf[2][0].x + a.y*qf[2][0].y + a.z*qf[2][0].z + a.w*qf[2][0].w
               + b.x*qf[2][1].x + b.y*qf[2][1].y + b.z*qf[2][1].z + b.w*qf[2][1].w;
            d3 = a.x*qf[3][0].x + a.y*qf[3][0].y + a.z*qf[3][0].z + a.w*qf[3][0].w
               + b.x*qf[3][1].x + b.y*qf[3][1].y + b.z*qf[3][1].z + b.w*qf[3][1].w;
        }
#pragma unroll
        for (int o = 4; o > 0; o >>= 1) {
            d0 += __shfl_xor_sync(0xffffffffu, d0, o);
            d1 += __shfl_xor_sync(0xffffffffu, d1, o);
            d2 += __shfl_xor_sync(0xffffffffu, d2, o);
            d3 += __shfl_xor_sync(0xffffffffu, d3, o);
        }
        if (l8 == 0) {
            sc[0][k] = d0 * SCALEF;
            sc[1][k] = d1 * SCALEF;
            sc[2][k] = d2 * SCALEF;
            sc[3][k] = d3 * SCALEF;
        }
    }
    __syncthreads();

    // softmax per query
    float inv[4];
#pragma unroll 1
    for (int s = 0; s < 4; s++) {
        float* scp = sc[s];
        float mx = -1e30f;
        for (int k = tid; k < Lx; k += 256) mx = fmaxf(mx, scp[k]);
        red[tid] = mx;
        __syncthreads();
        for (int st = 128; st > 0; st >>= 1) {
            if (tid < st) red[tid] = fmaxf(red[tid], red[tid + st]);
            __syncthreads();
        }
        mx = red[0];
        __syncthreads();
        float sum = 0.f;
        for (int k = tid; k < Lx; k += 256) {
            float e = __expf(scp[k] - mx);
            scp[k] = e;
            sum += e;
        }
        red[tid] = sum;
        __syncthreads();
        for (int st = 128; st > 0; st >>= 1) {
            if (tid < st) red[tid] += red[tid + st];
            __syncthreads();
        }
        inv[s] = 1.0f / red[0];
        __syncthreads();
    }

    // PV: each V load feeds 4 queries
    const int d = tid & 63, s4 = tid >> 6;
    float acc[4] = {0.f, 0.f, 0.f, 0.f};
    for (int k = s4; k < Lx; k += 4) {
        float v = g_V[((size_t)bh * Lx + k) * DHx + d];
        acc[0] += sc[0][k] * v;
        acc[1] += sc[1][k] * v;
        acc[2] += sc[2][k] * v;
        acc[3] += sc[3][k] * v;
    }
#pragma unroll
    for (int s = 0; s < 4; s++) red2[s][tid] = acc[s];
    __syncthreads();
    if (tid < 64) {
        float vm = g_Vsum[bh * DHx + d] * (1.0f / Lx);
#pragma unroll
        for (int s = 0; s < 4; s++) {
            if (!valid[s]) continue;
            float c = (red2[s][d] + red2[s][d + 64] + red2[s][d + 128] + red2[s][d + 192]) * inv[s];
            int i = blockIdx.x + NQB * s;
            g_delta[((size_t)bh * KTOP + i) * DHx + d] = c - vm;
        }
    }
}

// ---------------------------------------------------------------------------
__global__ void base_kernel(const float* __restrict__ Wo, const float* __restrict__ bo)
{
    int b = blockIdx.x, j = threadIdx.x;
    float acc = bo[j];
    for (int c = 0; c < Dx; c++) {
        int h = c >> 6, d = c & 63;
        acc += g_Vsum[(b * Hx + h) * DHx + d] * (1.0f / Lx) * Wo[(size_t)c * Dx + j];
    }
    g_base[b * Dx + j] = acc;
}

// fill: one float4 per thread, 2M float4s
__global__ void fill_kernel(float* __restrict__ out)
{
    size_t i4 = (size_t)blockIdx.x * 256 + threadIdx.x;
    int b = (int)(i4 >> 18);                 // / (Lx*Dx/4)
    int j4 = (int)(i4 & (Dx / 4 - 1));       // % 128
    *reinterpret_cast<float4*>(out + i4 * 4) =
        *reinterpret_cast<const float4*>(g_base + b * Dx + j4 * 4);
}

__global__ void scatter_kernel(const float* __restrict__ Wo, float* __restrict__ out)
{
    const int bh = blockIdx.y;
    const int i = blockIdx.x;
    const int j = threadIdx.x;  // 512
    const int b = bh >> 3, h = bh & 7;
    const int l = g_top[bh * KTOP + i];
    __shared__ float dl[DHx];
    if (j < 64) dl[j] = g_delta[((size_t)bh * KTOP + i) * DHx + j];
    __syncthreads();
    float acc = 0.f;
#pragma unroll 16
    for (int d = 0; d < 64; d++) acc += dl[d] * Wo[(size_t)(h * 64 + d) * Dx + j];
    atomicAdd(&out[((size_t)b * Lx + l) * Dx + j], acc);
}

// ---------------------------------------------------------------------------
extern "C" void kernel_launch(void* const* d_in, const int* in_sizes, int n_in,
                              void* d_out, int out_size)
{
    const float* x  = (const float*)d_in[0];
    const float* Wq = (const float*)d_in[1];
    const float* bq = (const float*)d_in[2];
    const float* Wk = (const float*)d_in[3];
    const float* bk = (const float*)d_in[4];
    const float* Wv = (const float*)d_in[5];
    const float* bv = (const float*)d_in[6];
    const float* Wo = (const float*)d_in[7];
    const float* bo = (const float*)d_in[8];
    float* out = (float*)d_out;

    (void)in_sizes; (void)n_in; (void)out_size;

    cudaFuncSetAttribute(proj_mma_kernel,
                         cudaFuncAttributeMaxDynamicSharedMemorySize, PROJ_SMEM);
    cudaFuncSetAttribute(score_mma_kernel,
                         cudaFuncAttributeMaxDynamicSharedMemorySize, SCORE_SMEM);

    prep_w_kernel<<<dim3(16, 16, 3), 256>>>(Wq, Wk, Wv);          // 0
    prep_x_kernel<<<(Bx * Lx * Dx / 4) / 256, 256>>>(x);          // 1
    zero_sums_kernel<<<(BHx * DHx + 255) / 256, 256>>>();         // 2

    dim3 pg(Dx / 64, (Bx * Lx) / 128, 3);   // (8, 64, 3)
    proj_mma_kernel<<<pg, 256, PROJ_SMEM>>>(bq, bk, bv);          // 3 <- ncu target

    partial_sums_kernel<<<dim3(BHx, 16), 256>>>();                // 4
    score_mma_kernel<<<dim3(Lx / 128, BHx), 256, SCORE_SMEM>>>(); // 5
    mstat_kernel<<<BHx * Lx / 256, 256>>>();                      // 6
    topk_kernel<<<BHx, 256>>>();                                  // 7
    sparse_attn_kernel<<<dim3(NQB, BHx), 256>>>();                // 8
    base_kernel<<<Bx, Dx>>>(Wo, bo);                              // 9
    fill_kernel<<<(Bx * Lx * Dx / 4) / 256, 256>>>(out);          // 10
    scatter_kernel<<<dim3(KTOP, BHx), Dx>>>(Wo, out);             // 11
}

// round 13
// speedup vs baseline: 1.4291x; 1.0254x over previous
#include <cuda_runtime.h>
#include <cuda_fp16.h>
#include <math.h>
#include <stdint.h>

#define Bx 4
#define Lx 2048
#define Dx 512
#define Hx 8
#define DHx 64
#define BHx 32
#define KTOP 38
#define NQB 10
#define SCALEF 0.125f
#define SH 72   // score smem halves per row
#define PSH 40  // proj stage halves per row

// ---------------- scratch (device globals; no allocation allowed) ----------
__device__ float  g_Q[BHx * Lx * DHx];
__device__ float  g_K[BHx * Lx * DHx];
__device__ float  g_V[BHx * Lx * DHx];
__device__ __half g_Xhi[Bx * Lx * Dx];
__device__ __half g_Xlo[Bx * Lx * Dx];
__device__ __half g_WThi[3 * Dx * Dx];
__device__ __half g_WTlo[3 * Dx * Dx];
__device__ __half g_Qhi[BHx * Lx * DHx];
__device__ __half g_Qlo[BHx * Lx * DHx];
__device__ __half g_Khi[BHx * Lx * DHx];
__device__ __half g_Klo[BHx * Lx * DHx];
__device__ float  g_rowmax[BHx * Lx];
__device__ float  g_M[BHx * Lx];
__device__ int    g_top[BHx * KTOP];
__device__ float  g_Ksum[BHx * DHx];
__device__ float  g_Vsum[BHx * DHx];
__device__ float  g_delta[BHx * KTOP * DHx];
__device__ float  g_base[Bx * Dx];

// ---------------- helpers ----------------------------------------------------
__device__ __forceinline__ void mma_f16(float c[4], const uint32_t a[4],
                                        uint32_t b0, uint32_t b1) {
    asm volatile(
        "mma.sync.aligned.m16n8k16.row.col.f32.f16.f16.f32 "
        "{%0,%1,%2,%3}, {%4,%5,%6,%7}, {%8,%9}, {%0,%1,%2,%3};"
        : "+f"(c[0]), "+f"(c[1]), "+f"(c[2]), "+f"(c[3])
        : "r"(a[0]), "r"(a[1]), "r"(a[2]), "r"(a[3]), "r"(b0), "r"(b1));
}
__device__ __forceinline__ void ldm_x4(uint32_t r[4], uint32_t saddr) {
    asm volatile("ldmatrix.sync.aligned.m8n8.x4.shared.b16 {%0,%1,%2,%3}, [%4];"
        : "=r"(r[0]), "=r"(r[1]), "=r"(r[2]), "=r"(r[3]) : "r"(saddr));
}
__device__ __forceinline__ void ldm_x2(uint32_t r[2], uint32_t saddr) {
    asm volatile("ldmatrix.sync.aligned.m8n8.x2.shared.b16 {%0,%1}, [%2];"
        : "=r"(r[0]), "=r"(r[1]) : "r"(saddr));
}
__device__ __forceinline__ void split_h(float f, __half& h, __half& l) {
    h = __float2half_rn(f);
    l = __float2half_rn(f - __half2float(h));
}
__device__ __forceinline__ uint32_t smem_u32(const void* p) {
    uint32_t a;
    asm("{ .reg .u64 t; cvta.to.shared.u64 t, %1; cvt.u32.u64 %0, t; }"
        : "=r"(a) : "l"(p));
    return a;
}
__device__ __forceinline__ void cp16(uint32_t s, const void* g) {
    asm volatile("cp.async.cg.shared.global [%0], [%1], 16;" :: "r"(s), "l"(g));
}
#define CP_COMMIT() asm volatile("cp.async.commit_group;" ::: "memory")
#define CP_WAIT(N)  asm volatile("cp.async.wait_group %0;" :: "n"(N) : "memory")

// ---------------------------------------------------------------------------
// prep_w: transpose W[k][c] -> WT[c][k], split fp16 hi/lo. grid(16,16,3).
// ---------------------------------------------------------------------------
__global__ void prep_w_kernel(const float* __restrict__ Wq,
                              const float* __restrict__ Wk,
                              const float* __restrict__ Wv)
{
    __shared__ float s[32][33];
    const float* W = (blockIdx.z == 0) ? Wq : (blockIdx.z == 1) ? Wk : Wv;
    __half* dh = g_WThi + (size_t)blockIdx.z * Dx * Dx;
    __half* dl = g_WTlo + (size_t)blockIdx.z * Dx * Dx;
    const int kt = blockIdx.y * 32, ct = blockIdx.x * 32;
    const int tid = threadIdx.x;
    {
        int r = tid >> 3, c4 = (tid & 7) * 4;
        float4 v = *reinterpret_cast<const float4*>(&W[(size_t)(kt + r) * Dx + ct + c4]);
        s[r][c4] = v.x; s[r][c4 + 1] = v.y; s[r][c4 + 2] = v.z; s[r][c4 + 3] = v.w;
    }
    __syncthreads();
    {
        int cw = tid >> 3, k4 = (tid & 7) * 4;
        size_t o = (size_t)(ct + cw) * Dx + kt + k4;
#pragma unroll
        for (int j = 0; j < 4; j += 2) {
            __half h0, l0, h1, l1;
            split_h(s[k4 + j][cw], h0, l0);
            split_h(s[k4 + j + 1][cw], h1, l1);
            *reinterpret_cast<__half2*>(&dh[o + j]) = __halves2half2(h0, h1);
            *reinterpret_cast<__half2*>(&dl[o + j]) = __halves2half2(l0, l1);
        }
    }
}

// ---------------------------------------------------------------------------
// prep_x: split x to fp16 hi/lo.
// ---------------------------------------------------------------------------
__global__ void prep_x_kernel(const float* __restrict__ X)
{
    size_t i4 = (size_t)blockIdx.x * 256 + threadIdx.x;
    float4 v = *reinterpret_cast<const float4*>(X + i4 * 4);
    __half h0, l0, h1, l1, h2, l2, h3, l3;
    split_h(v.x, h0, l0); split_h(v.y, h1, l1);
    split_h(v.z, h2, l2); split_h(v.w, h3, l3);
    size_t o = i4 * 4;
    *reinterpret_cast<__half2*>(&g_Xhi[o])     = __halves2half2(h0, h1);
    *reinterpret_cast<__half2*>(&g_Xhi[o + 2]) = __halves2half2(h2, h3);
    *reinterpret_cast<__half2*>(&g_Xlo[o])     = __halves2half2(l0, l1);
    *reinterpret_cast<__half2*>(&g_Xlo[o + 2]) = __halves2half2(l2, l3);
}

// ---------------------------------------------------------------------------
// proj_mma: Y = X @ W + b; block 128m x 64n, BK=32, 3-stage cp.async,
// ONE barrier per iter, ldmatrix fragments.
// ---------------------------------------------------------------------------
#define PROJ_STAGE ((2 * 128 + 2 * 64) * PSH)      // halves per stage (15360)
#define PROJ_SMEM  (3 * PROJ_STAGE * 2)            // 92160 B

__global__ __launch_bounds__(256, 2)
void proj_mma_kernel(const float* __restrict__ bq, const float* __restrict__ bk,
                     const float* __restrict__ bv)
{
    extern __shared__ __half smh[];
    const int tid = threadIdx.x;
    const int w = tid >> 5, lane = tid & 31;
    const int gr = lane >> 2, tc = lane & 3;
    const int wm = w >> 1, wn = w & 1;
    const int mbase = blockIdx.y * 128;
    const int nbase = blockIdx.x * 64;
    const int z = blockIdx.z;

    const __half* WTh = g_WThi + (size_t)z * Dx * Dx;
    const __half* WTl = g_WTlo + (size_t)z * Dx * Dx;
    const float* bias = (z == 0) ? bq : (z == 1) ? bk : bv;
    float* out = (z == 0) ? g_Q : (z == 1) ? g_K : g_V;
    __half* outHi = (z == 0) ? g_Qhi : (z == 1) ? g_Khi : (__half*)0;
    __half* outLo = (z == 0) ? g_Qlo : (z == 1) ? g_Klo : (__half*)0;

    const uint32_t sb0 = smem_u32(smh);

    auto prefetch = [&](int kt_i, int stage) {
        const int kt = kt_i * 32;
        const uint32_t sb = sb0 + (uint32_t)(stage * PROJ_STAGE * 2);
#pragma unroll
        for (int i = 0; i < 6; i++) {
            int idx = tid + i * 256;
            const __half* gp;
            uint32_t soff;
            if (idx < 512) {
                int r = idx >> 2, u = (idx & 3) * 8;
                soff = (uint32_t)(r * PSH + u);
                gp = g_Xhi + (size_t)(mbase + r) * Dx + kt + u;
            } else if (idx < 1024) {
                int v = idx - 512;
                int r = v >> 2, u = (v & 3) * 8;
                soff = (uint32_t)(128 * PSH + r * PSH + u);
                gp = g_Xlo + (size_t)(mbase + r) * Dx + kt + u;
            } else if (idx < 1280) {
                int v = idx - 1024;
                int r = v >> 2, u = (v & 3) * 8;
                soff = (uint32_t)(256 * PSH + r * PSH + u);
                gp = WTh + (size_t)(nbase + r) * Dx + kt + u;
            } else {
                int v = idx - 1280;
                int r = v >> 2, u = (v & 3) * 8;
                soff = (uint32_t)(256 * PSH + 64 * PSH + r * PSH + u);
                gp = WTl + (size_t)(nbase + r) * Dx + kt + u;
            }
            cp16(sb + soff * 2, gp);
        }
        CP_COMMIT();
    };

    // per-thread ldmatrix byte offsets within a stage
    const uint32_t offA = (uint32_t)(((wm * 32 + (lane & 15)) * PSH + (lane >> 4) * 8) * 2);
    const uint32_t offB = (uint32_t)(((wn * 32 + (lane & 7)) * PSH + ((lane >> 3) & 1) * 8) * 2);
    const uint32_t xh_off = 0, xl_off = 128 * PSH * 2;
    const uint32_t wh_off = 256 * PSH * 2, wl_off = (256 + 64) * PSH * 2;

    float C[8][4];
#pragma unroll
    for (int p = 0; p < 8; p++)
#pragma unroll
        for (int j = 0; j < 4; j++) C[p][j] = 0.f;

    prefetch(0, 0);
    prefetch(1, 1);

    for (int it = 0; it < 16; it++) {
        const int stage = it % 3;
        if (it < 15) CP_WAIT(1); else CP_WAIT(0);
        __syncthreads();
        if (it + 2 < 16) prefetch(it + 2, (it + 2) % 3);

        const uint32_t sb = sb0 + (uint32_t)(stage * PROJ_STAGE * 2);

#pragma unroll
        for (int k16 = 0; k16 < 2; k16++) {
            const uint32_t ko = (uint32_t)(k16 * 16 * 2);   // byte offset along k
            uint32_t ah[2][4], al[2][4];
#pragma unroll
            for (int mi = 0; mi < 2; mi++) {
                uint32_t ra = sb + offA + (uint32_t)(mi * 16 * PSH * 2) + ko;
                ldm_x4(ah[mi], ra + xh_off);
                ldm_x4(al[mi], ra + xl_off);
            }
#pragma unroll
            for (int ni = 0; ni < 4; ni++) {
                uint32_t rb = sb + offB + (uint32_t)(ni * 8 * PSH * 2) + ko;
                uint32_t bh[2], bl[2];
                ldm_x2(bh, rb + wh_off);
                ldm_x2(bl, rb + wl_off);
#pragma unroll
                for (int mi = 0; mi < 2; mi++) {
                    mma_f16(C[mi * 4 + ni], ah[mi], bh[0], bh[1]);
                    mma_f16(C[mi * 4 + ni], ah[mi], bl[0], bl[1]);
                    mma_f16(C[mi * 4 + ni], al[mi], bh[0], bh[1]);
                }
            }
        }
    }

#pragma unroll
    for (int mi = 0; mi < 2; mi++) {
#pragma unroll
        for (int ni = 0; ni < 4; ni++) {
            const float* c = C[mi * 4 + ni];
            int col = nbase + (wn * 4 + ni) * 8 + 2 * tc;
            int h = col >> 6, d = col & 63;
            float b0 = bias[col], b1 = bias[col + 1];
#pragma unroll
            for (int half_ = 0; half_ < 2; half_++) {
                int r = mbase + (wm * 2 + mi) * 16 + gr + half_ * 8;
                int bb = r >> 11, l = r & 2047;
                size_t o = (((size_t)(bb * Hx + h)) * Lx + l) * DHx + d;
                float v0 = c[half_ * 2] + b0;
                float v1 = c[half_ * 2 + 1] + b1;
                *reinterpret_cast<float2*>(&out[o]) = make_float2(v0, v1);
                if (outHi) {
                    __half h0, l0, h1, l1;
                    split_h(v0, h0, l0);
                    split_h(v1, h1, l1);
                    *reinterpret_cast<__half2*>(&outHi[o]) = __halves2half2(h0, h1);
                    *reinterpret_cast<__half2*>(&outLo[o]) = __halves2half2(l0, l1);
                }
            }
        }
    }
}

// ---------------------------------------------------------------------------
// score_mma: rowmax(Q[128,64] @ K^T). 64 keys/stage, 3-stage cp.async,
// one barrier per iter, ldmatrix fragments.
// ---------------------------------------------------------------------------
#define KSTAGE (2 * 64 * SH)    // halves per K stage (9216)
#define SCORE_SMEM ((2 * 128 * SH + 3 * KSTAGE) * 2 + 2 * 128 * 4)

__global__ __launch_bounds__(256, 2)
void score_mma_kernel()
{
    extern __shared__ __half smh[];
    __half* Qh = smh;
    __half* Ql = Qh + 128 * SH;
    __half* Kst = Ql + 128 * SH;             // 3 stages follow
    float* red = reinterpret_cast<float*>(Kst + 3 * KSTAGE);

    const int tid = threadIdx.x;
    const int w = tid >> 5, lane = tid & 31;
    const int gr = lane >> 2, tc = lane & 3;
    const int wm = w >> 1, wn = w & 1;
    const int bh = blockIdx.y;
    const int qbase = blockIdx.x * 128;

    const uint32_t q_u32 = smem_u32(Qh);
    const uint32_t kst_u32 = smem_u32(Kst);

    auto prefetch_k = [&](int t, int stage) {
        const uint32_t sb = kst_u32 + (uint32_t)(stage * KSTAGE * 2);
#pragma unroll
        for (int i = 0; i < 4; i++) {
            int idx = tid + i * 256;
            int buf = idx >> 9;
            int within = idx & 511;
            int r = within >> 3;
            int u = (within & 7) * 8;
            uint32_t sa = sb + (uint32_t)((buf * 64 * SH + r * SH + u) * 2);
            const __half* gp = (buf == 0 ? g_Khi : g_Klo)
                               + ((size_t)bh * Lx + t * 64 + r) * DHx + u;
            cp16(sa, gp);
        }
        CP_COMMIT();
    };

    // Q fill once
#pragma unroll
    for (int i = 0; i < 4; i++) {
        int idx = tid + i * 256;
        int r = idx >> 3;
        int u = (idx & 7) * 8;
        size_t qs = ((size_t)bh * Lx + qbase + r) * DHx + u;
        *reinterpret_cast<uint4*>(Qh + r * SH + u) =
            *reinterpret_cast<const uint4*>(g_Qhi + qs);
        *reinterpret_cast<uint4*>(Ql + r * SH + u) =
            *reinterpret_cast<const uint4*>(g_Qlo + qs);
    }

    prefetch_k(0, 0);
    prefetch_k(1, 1);

    // ldmatrix offsets
    const uint32_t offA = (uint32_t)(((wm * 32 + (lane & 15)) * SH + (lane >> 4) * 8) * 2);
    const uint32_t offB = (uint32_t)(((wn * 32 + (lane & 7)) * SH + ((lane >> 3) & 1) * 8) * 2);
    const uint32_t ql_off = 128 * SH * 2;
    const uint32_t kl_off = 64 * SH * 2;

    float rm0[2], rm1[2];
#pragma unroll
    for (int mi = 0; mi < 2; mi++) { rm0[mi] = -1e30f; rm1[mi] = -1e30f; }

    for (int t = 0; t < 32; t++) {
        const int stage = t % 3;
        if (t < 31) CP_WAIT(1); else CP_WAIT(0);
        __syncthreads();
        if (t + 2 < 32) prefetch_k(t + 2, (t + 2) % 3);

        const uint32_t ksb = kst_u32 + (uint32_t)(stage * KSTAGE * 2);

        float C[8][4];
#pragma unroll
        for (int p = 0; p < 8; p++)
#pragma unroll
            for (int j = 0; j < 4; j++) C[p][j] = 0.f;

#pragma unroll
        for (int k16 = 0; k16 < 4; k16++) {
            const uint32_t ko = (uint32_t)(k16 * 16 * 2);
            uint32_t ah[2][4], al[2][4];
#pragma unroll
            for (int mi = 0; mi < 2; mi++) {
                uint32_t ra = q_u32 + offA + (uint32_t)(mi * 16 * SH * 2) + ko;
                ldm_x4(ah[mi], ra);
                ldm_x4(al[mi], ra + ql_off);
            }
#pragma unroll
            for (int ni = 0; ni < 4; ni++) {
                uint32_t rb = ksb + offB + (uint32_t)(ni * 8 * SH * 2) + ko;
                uint32_t bh2[2], bl2[2];
                ldm_x2(bh2, rb);
                ldm_x2(bl2, rb + kl_off);
#pragma unroll
                for (int mi = 0; mi < 2; mi++) {
                    mma_f16(C[mi * 4 + ni], ah[mi], bh2[0], bh2[1]);
                    mma_f16(C[mi * 4 + ni], ah[mi], bl2[0], bl2[1]);
                    mma_f16(C[mi * 4 + ni], al[mi], bh2[0], bh2[1]);
                }
            }
        }

#pragma unroll
        for (int mi = 0; mi < 2; mi++)
#pragma unroll
            for (int ni = 0; ni < 4; ni++) {
                const float* c = C[mi * 4 + ni];
                rm0[mi] = fmaxf(rm0[mi], fmaxf(c[0], c[1]));
                rm1[mi] = fmaxf(rm1[mi], fmaxf(c[2], c[3]));
            }
    }

#pragma unroll
    for (int mi = 0; mi < 2; mi++) {
        rm0[mi] = fmaxf(rm0[mi], __shfl_xor_sync(0xffffffffu, rm0[mi], 1));
        rm0[mi] = fmaxf(rm0[mi], __shfl_xor_sync(0xffffffffu, rm0[mi], 2));
        rm1[mi] = fmaxf(rm1[mi], __shfl_xor_sync(0xffffffffu, rm1[mi], 1));
        rm1[mi] = fmaxf(rm1[mi], __shfl_xor_sync(0xffffffffu, rm1[mi], 2));
    }
    __syncthreads();   // C consumed; red reuse safe
    if (tc == 0) {
#pragma unroll
        for (int mi = 0; mi < 2; mi++) {
            int row = (wm * 2 + mi) * 16 + gr;
            red[wn * 128 + row] = rm0[mi];
            red[wn * 128 + row + 8] = rm1[mi];
        }
    }
    __syncthreads();
    if (tid < 128) {
        float m = fmaxf(red[tid], red[128 + tid]);
        g_rowmax[(size_t)bh * Lx + qbase + tid] = m;
    }
}

// ---------------------------------------------------------------------------
// K / V column sums.
// ---------------------------------------------------------------------------
__global__ void zero_sums_kernel()
{
    int i = blockIdx.x * blockDim.x + threadIdx.x;
    if (i < BHx * DHx) { g_Ksum[i] = 0.f; g_Vsum[i] = 0.f; }
}

__global__ void partial_sums_kernel()
{
    const int bh = blockIdx.x;
    const int kb = blockIdx.y * 128;
    const int tid = threadIdx.x;
    const int d = tid & 63, s = tid >> 6;
    float ks = 0.f, vs = 0.f;
    for (int k = kb + s; k < kb + 128; k += 4) {
        ks += g_K[((size_t)bh * Lx + k) * DHx + d];
        vs += g_V[((size_t)bh * Lx + k) * DHx + d];
    }
    __shared__ float red[2][256];
    red[0][tid] = ks;
    red[1][tid] = vs;
    __syncthreads();
    if (tid < 64) {
        float a = red[0][d] + red[0][d + 64] + red[0][d + 128] + red[0][d + 192];
        float b = red[1][d] + red[1][d + 64] + red[1][d + 128] + red[1][d + 192];
        atomicAdd(&g_Ksum[bh * DHx + d], a);
        atomicAdd(&g_Vsum[bh * DHx + d], b);
    }
}

// ---------------------------------------------------------------------------
// M = SCALE * (rowmax - Q.Ksum / L)
// ---------------------------------------------------------------------------
__global__ void mstat_kernel()
{
    int gidx = blockIdx.x * 256 + threadIdx.x;
    int bh = gidx >> 11;
    const float* qp = g_Q + (size_t)gidx * DHx;
    const float* ks = g_Ksum + bh * DHx;
    float dot = 0.f;
#pragma unroll
    for (int d = 0; d < DHx; d += 4) {
        float4 a = *reinterpret_cast<const float4*>(qp + d);
        float4 b = *reinterpret_cast<const float4*>(ks + d);
        dot += a.x * b.x + a.y * b.y + a.z * b.z + a.w * b.w;
    }
    g_M[gidx] = SCALEF * (g_rowmax[gidx] - dot * (1.0f / Lx));
}

// ---------------------------------------------------------------------------
// Top-38 selection per bh.
// ---------------------------------------------------------------------------
__global__ void topk_kernel()
{
    int bh = blockIdx.x;
    int tid = threadIdx.x;
    __shared__ float vals[Lx];
    __shared__ float rv[256];
    __shared__ int ri[256];
    for (int i = tid; i < Lx; i += 256) vals[i] = g_M[(size_t)bh * Lx + i];
    __syncthreads();
    for (int it = 0; it < KTOP; it++) {
        float best = -1e30f;
        int bidx = 0;
        for (int i = tid; i < Lx; i += 256) {
            float v = vals[i];
            if (v > best) { best = v; bidx = i; }
        }
        rv[tid] = best;
        ri[tid] = bidx;
        __syncthreads();
        for (int s = 128; s > 0; s >>= 1) {
            if (tid < s) {
                if (rv[tid + s] > rv[tid] ||
                    (rv[tid + s] == rv[tid] && ri[tid + s] < ri[tid])) {
                    rv[tid] = rv[tid + s];
                    ri[tid] = ri[tid + s];
                }
            }
            __syncthreads();
        }
        if (tid == 0) {
            g_top[bh * KTOP + it] = ri[0];
            vals[ri[0]] = -1e30f;
        }
        __syncthreads();
    }
}

// ---------------------------------------------------------------------------
// Sparse attention, 4 queries per block, quarter-warp QK (exact fp32).
// ---------------------------------------------------------------------------
__global__ __launch_bounds__(256)
void sparse_attn_kernel()
{
    const int bh = blockIdx.y;
    const int tid = threadIdx.x;
    const int warp = tid >> 5, lane = tid & 31;
    const int qq = lane >> 3;
    const int l8 = lane & 7;

    __shared__ float sc[4][Lx];
    __shared__ float qrow[4][DHx];
    __shared__ float red[256];
    __shared__ float red2[4][256];

    int qidx[4];
    bool valid[4];
#pragma unroll
    for (int s = 0; s < 4; s++) {
        int i = blockIdx.x + NQB * s;
        valid[s] = (i < KTOP);
        qidx[s] = valid[s] ? g_top[bh * KTOP + i] : 0;
    }

    if (tid < 256) {
        int s = tid >> 6, d = tid & 63;
        qrow[s][d] = valid[s] ? g_Q[((size_t)bh * Lx + qidx[s]) * DHx + d] : 0.f;
    }
    __syncthreads();

    float4 qf[4][2];
#pragma unroll
    for (int s = 0; s < 4; s++) {
        qf[s][0] = *reinterpret_cast<const float4*>(&qrow[s][l8 * 8]);
        qf[s][1] = *reinterpret_cast<const float4*>(&qrow[s][l8 * 8 + 4]);
    }

    for (int it = 0; it < Lx / 32; it++) {
        int k = it * 32 + warp * 4 + qq;
        const float* kr = g_K + ((size_t)bh * Lx + k) * DHx;
        float4 a = *reinterpret_cast<const float4*>(kr + l8 * 8);
        float4 b = *reinterpret_cast<const float4*>(kr + l8 * 8 + 4);
        float d0, d1, d2, d3;
        d0 = a.x*qf[0][0].x + a.y*qf[0][0].y + a.z*qf[0][0].z + a.w*qf[0][0].w
           + b.x*qf[0][1].x + b.y*qf[0][1].y + b.z*qf[0][1].z + b.w*qf[0][1].w;
        d1 = a.x*qf[1][0].x + a.y*qf[1][0].y + a.z*qf[1][0].z + a.w*qf[1][0].w
           + b.x*qf[1][1].x + b.y*qf[1][1].y + b.z*qf[1][1].z + b.w*qf[1][1].w;
        d2 = a.x*qf[2][0].x + a.y*qf[2][0].y + a.z*qf[2][0].z + a.w*qf[2][0].w
           + b.x*qf[2][1].x + b.y*qf[2][1].y + b.z*qf[2][1].z + b.w*qf[2][1].w;
        d3 = a.x*qf[3][0].x + a.y*qf[3][0].y + a.z*qf[3][0].z + a.w*qf[3][0].w
           + b.x*qf[3][1].x + b.y*qf[3][1].y + b.z*qf[3][1].z + b.w*qf[3][1].w;
#pragma unroll
        for (int o = 4; o > 0; o >>= 1) {
            d0 += __shfl_xor_sync(0xffffffffu, d0, o);
            d1 += __shfl_xor_sync(0xffffffffu, d1, o);
            d2 += __shfl_xor_sync(0xffffffffu, d2, o);
            d3 += __shfl_xor_sync(0xffffffffu, d3, o);
        }
        if (l8 == 0) {
            sc[0][k] = d0 * SCALEF;
            sc[1][k] = d1 * SCALEF;
            sc[2][k] = d2 * SCALEF;
            sc[3][k] = d3 * SCALEF;
        }
    }
    __syncthreads();

    float inv[4];
#pragma unroll 1
    for (int s = 0; s < 4; s++) {
        float* scp = sc[s];
        float mx = -1e30f;
        for (int k = tid; k < Lx; k += 256) mx = fmaxf(mx, scp[k]);
        red[tid] = mx;
        __syncthreads();
        for (int st = 128; st > 0; st >>= 1) {
            if (tid < st) red[tid] = fmaxf(red[tid], red[tid + st]);
            __syncthreads();
        }
        mx = red[0];
        __syncthreads();
        float sum = 0.f;
        for (int k = tid; k < Lx; k += 256) {
            float e = __expf(scp[k] - mx);
            scp[k] = e;
            sum += e;
        }
        red[tid] = sum;
        __syncthreads();
        for (int st = 128; st > 0; st >>= 1) {
            if (tid < st) red[tid] += red[tid + st];
            __syncthreads();
        }
        inv[s] = 1.0f / red[0];
        __syncthreads();
    }

    const int d = tid & 63, s4 = tid >> 6;
    float acc[4] = {0.f, 0.f, 0.f, 0.f};
    for (int k = s4; k < Lx; k += 4) {
        float v = g_V[((size_t)bh * Lx + k) * DHx + d];
        acc[0] += sc[0][k] * v;
        acc[1] += sc[1][k] * v;
        acc[2] += sc[2][k] * v;
        acc[3] += sc[3][k] * v;
    }
#pragma unroll
    for (int s = 0; s < 4; s++) red2[s][tid] = acc[s];
    __syncthreads();
    if (tid < 64) {
        float vm = g_Vsum[bh * DHx + d] * (1.0f / Lx);
#pragma unroll
        for (int s = 0; s < 4; s++) {
            if (!valid[s]) continue;
            float c = (red2[s][d] + red2[s][d + 64] + red2[s][d + 128] + red2[s][d + 192]) * inv[s];
            int i = blockIdx.x + NQB * s;
            g_delta[((size_t)bh * KTOP + i) * DHx + d] = c - vm;
        }
    }
}

// ---------------------------------------------------------------------------
__global__ void base_kernel(const float* __restrict__ Wo, const float* __restrict__ bo)
{
    int b = blockIdx.x, j = threadIdx.x;
    float acc = bo[j];
    for (int c = 0; c < Dx; c++) {
        int h = c >> 6, d = c & 63;
        acc += g_Vsum[(b * Hx + h) * DHx + d] * (1.0f / Lx) * Wo[(size_t)c * Dx + j];
    }
    g_base[b * Dx + j] = acc;
}

__global__ void fill_kernel(float* __restrict__ out)
{
    size_t i4 = (size_t)blockIdx.x * 256 + threadIdx.x;
    int b = (int)(i4 >> 18);
    int j4 = (int)(i4 & (Dx / 4 - 1));
    *reinterpret_cast<float4*>(out + i4 * 4) =
        *reinterpret_cast<const float4*>(g_base + b * Dx + j4 * 4);
}

__global__ void scatter_kernel(const float* __restrict__ Wo, float* __restrict__ out)
{
    const int bh = blockIdx.y;
    const int i = blockIdx.x;
    const int j = threadIdx.x;
    const int b = bh >> 3, h = bh & 7;
    const int l = g_top[bh * KTOP + i];
    __shared__ float dl[DHx];
    if (j < 64) dl[j] = g_delta[((size_t)bh * KTOP + i) * DHx + j];
    __syncthreads();
    float acc = 0.f;
#pragma unroll 16
    for (int d = 0; d < 64; d++) acc += dl[d] * Wo[(size_t)(h * 64 + d) * Dx + j];
    atomicAdd(&out[((size_t)b * Lx + l) * Dx + j], acc);
}

// ---------------------------------------------------------------------------
extern "C" void kernel_launch(void* const* d_in, const int* in_sizes, int n_in,
                              void* d_out, int out_size)
{
    const float* x  = (const float*)d_in[0];
    const float* Wq = (const float*)d_in[1];
    const float* bq = (const float*)d_in[2];
    const float* Wk = (const float*)d_in[3];
    const float* bk = (const float*)d_in[4];
    const float* Wv = (const float*)d_in[5];
    const float* bv = (const float*)d_in[6];
    const float* Wo = (const float*)d_in[7];
    const float* bo = (const float*)d_in[8];
    float* out = (float*)d_out;

    (void)in_sizes; (void)n_in; (void)out_size;

    cudaFuncSetAttribute(proj_mma_kernel,
                         cudaFuncAttributeMaxDynamicSharedMemorySize, PROJ_SMEM);
    cudaFuncSetAttribute(score_mma_kernel,
                         cudaFuncAttributeMaxDynamicSharedMemorySize, SCORE_SMEM);

    prep_w_kernel<<<dim3(16, 16, 3), 256>>>(Wq, Wk, Wv);          // 0
    prep_x_kernel<<<(Bx * Lx * Dx / 4) / 256, 256>>>(x);          // 1
    zero_sums_kernel<<<(BHx * DHx + 255) / 256, 256>>>();         // 2

    dim3 pg(Dx / 64, (Bx * Lx) / 128, 3);   // (8, 64, 3)
    proj_mma_kernel<<<pg, 256, PROJ_SMEM>>>(bq, bk, bv);          // 3 <- ncu target

    partial_sums_kernel<<<dim3(BHx, 16), 256>>>();                // 4
    score_mma_kernel<<<dim3(Lx / 128, BHx), 256, SCORE_SMEM>>>(); // 5
    mstat_kernel<<<BHx * Lx / 256, 256>>>();                      // 6
    topk_kernel<<<BHx, 256>>>();                                  // 7
    sparse_attn_kernel<<<dim3(NQB, BHx), 256>>>();                // 8
    base_kernel<<<Bx, Dx>>>(Wo, bo);                              // 9
    fill_kernel<<<(Bx * Lx * Dx / 4) / 256, 256>>>(out);          // 10
    scatter_kernel<<<dim3(KTOP, BHx), Dx>>>(Wo, out);             // 11
}

// round 14
// speedup vs baseline: 1.4412x; 1.0085x over previous
#include <cuda_runtime.h>
#include <cuda_fp16.h>
#include <math.h>
#include <stdint.h>

#define Bx 4
#define Lx 2048
#define Dx 512
#define Hx 8
#define DHx 64
#define BHx 32
#define KTOP 38
#define NQB 10
#define SCALEF 0.125f
#define SH 72   // score smem halves per row
#define PSH 40  // proj stage halves per row

// ---------------- scratch (device globals; no allocation allowed) ----------
__device__ float  g_Q[BHx * Lx * DHx];
__device__ float  g_K[BHx * Lx * DHx];
__device__ float  g_V[BHx * Lx * DHx];
__device__ __half g_Xhi[Bx * Lx * Dx];
__device__ __half g_Xlo[Bx * Lx * Dx];
__device__ __half g_WThi[3 * Dx * Dx];
__device__ __half g_WTlo[3 * Dx * Dx];
__device__ __half g_Qhi[BHx * Lx * DHx];
__device__ __half g_Qlo[BHx * Lx * DHx];
__device__ __half g_Khi[BHx * Lx * DHx];
__device__ __half g_Klo[BHx * Lx * DHx];
__device__ float  g_rowmax[BHx * Lx];
__device__ float  g_M[BHx * Lx];
__device__ int    g_top[BHx * KTOP];
__device__ float  g_Ksum[BHx * DHx];
__device__ float  g_Vsum[BHx * DHx];
__device__ float  g_delta[BHx * KTOP * DHx];
__device__ float  g_base[Bx * Dx];

// ---------------- helpers ----------------------------------------------------
__device__ __forceinline__ void mma_f16(float c[4], const uint32_t a[4],
                                        uint32_t b0, uint32_t b1) {
    asm volatile(
        "mma.sync.aligned.m16n8k16.row.col.f32.f16.f16.f32 "
        "{%0,%1,%2,%3}, {%4,%5,%6,%7}, {%8,%9}, {%0,%1,%2,%3};"
        : "+f"(c[0]), "+f"(c[1]), "+f"(c[2]), "+f"(c[3])
        : "r"(a[0]), "r"(a[1]), "r"(a[2]), "r"(a[3]), "r"(b0), "r"(b1));
}
__device__ __forceinline__ void ldm_x4(uint32_t r[4], uint32_t saddr) {
    asm volatile("ldmatrix.sync.aligned.m8n8.x4.shared.b16 {%0,%1,%2,%3}, [%4];"
        : "=r"(r[0]), "=r"(r[1]), "=r"(r[2]), "=r"(r[3]) : "r"(saddr));
}
__device__ __forceinline__ void split_h(float f, __half& h, __half& l) {
    h = __float2half_rn(f);
    l = __float2half_rn(f - __half2float(h));
}
__device__ __forceinline__ uint32_t smem_u32(const void* p) {
    uint32_t a;
    asm("{ .reg .u64 t; cvta.to.shared.u64 t, %1; cvt.u32.u64 %0, t; }"
        : "=r"(a) : "l"(p));
    return a;
}
__device__ __forceinline__ void cp16(uint32_t s, const void* g) {
    asm volatile("cp.async.cg.shared.global [%0], [%1], 16;" :: "r"(s), "l"(g));
}
#define CP_COMMIT() asm volatile("cp.async.commit_group;" ::: "memory")
#define CP_WAIT(N)  asm volatile("cp.async.wait_group %0;" :: "n"(N) : "memory")

// ---------------------------------------------------------------------------
// prep_w: transpose W[k][c] -> WT[c][k], split fp16 hi/lo. grid(16,16,3).
// ---------------------------------------------------------------------------
__global__ void prep_w_kernel(const float* __restrict__ Wq,
                              const float* __restrict__ Wk,
                              const float* __restrict__ Wv)
{
    __shared__ float s[32][33];
    const float* W = (blockIdx.z == 0) ? Wq : (blockIdx.z == 1) ? Wk : Wv;
    __half* dh = g_WThi + (size_t)blockIdx.z * Dx * Dx;
    __half* dl = g_WTlo + (size_t)blockIdx.z * Dx * Dx;
    const int kt = blockIdx.y * 32, ct = blockIdx.x * 32;
    const int tid = threadIdx.x;
    {
        int r = tid >> 3, c4 = (tid & 7) * 4;
        float4 v = *reinterpret_cast<const float4*>(&W[(size_t)(kt + r) * Dx + ct + c4]);
        s[r][c4] = v.x; s[r][c4 + 1] = v.y; s[r][c4 + 2] = v.z; s[r][c4 + 3] = v.w;
    }
    __syncthreads();
    {
        int cw = tid >> 3, k4 = (tid & 7) * 4;
        size_t o = (size_t)(ct + cw) * Dx + kt + k4;
#pragma unroll
        for (int j = 0; j < 4; j += 2) {
            __half h0, l0, h1, l1;
            split_h(s[k4 + j][cw], h0, l0);
            split_h(s[k4 + j + 1][cw], h1, l1);
            *reinterpret_cast<__half2*>(&dh[o + j]) = __halves2half2(h0, h1);
            *reinterpret_cast<__half2*>(&dl[o + j]) = __halves2half2(l0, l1);
        }
    }
}

// ---------------------------------------------------------------------------
// prep_x: split x to fp16 hi/lo.
// ---------------------------------------------------------------------------
__global__ void prep_x_kernel(const float* __restrict__ X)
{
    size_t i4 = (size_t)blockIdx.x * 256 + threadIdx.x;
    float4 v = *reinterpret_cast<const float4*>(X + i4 * 4);
    __half h0, l0, h1, l1, h2, l2, h3, l3;
    split_h(v.x, h0, l0); split_h(v.y, h1, l1);
    split_h(v.z, h2, l2); split_h(v.w, h3, l3);
    size_t o = i4 * 4;
    *reinterpret_cast<__half2*>(&g_Xhi[o])     = __halves2half2(h0, h1);
    *reinterpret_cast<__half2*>(&g_Xhi[o + 2]) = __halves2half2(h2, h3);
    *reinterpret_cast<__half2*>(&g_Xlo[o])     = __halves2half2(l0, l1);
    *reinterpret_cast<__half2*>(&g_Xlo[o + 2]) = __halves2half2(l2, l3);
}

// ---------------------------------------------------------------------------
// proj_mma: Y = X @ W + b; block 128m x 64n, BK=32, 3-stage cp.async,
// ldmatrix x4 for A and B, pass-major MMA issue (no back-to-back C reuse).
// ---------------------------------------------------------------------------
#define PROJ_STAGE ((2 * 128 + 2 * 64) * PSH)
#define PROJ_SMEM  (3 * PROJ_STAGE * 2)

__global__ __launch_bounds__(256, 2)
void proj_mma_kernel(const float* __restrict__ bq, const float* __restrict__ bk,
                     const float* __restrict__ bv)
{
    extern __shared__ __half smh[];
    const int tid = threadIdx.x;
    const int w = tid >> 5, lane = tid & 31;
    const int gr = lane >> 2, tc = lane & 3;
    const int wm = w >> 1, wn = w & 1;
    const int mbase = blockIdx.y * 128;
    const int nbase = blockIdx.x * 64;
    const int z = blockIdx.z;

    const __half* WTh = g_WThi + (size_t)z * Dx * Dx;
    const __half* WTl = g_WTlo + (size_t)z * Dx * Dx;
    const float* bias = (z == 0) ? bq : (z == 1) ? bk : bv;
    float* out = (z == 0) ? g_Q : (z == 1) ? g_K : g_V;
    __half* outHi = (z == 0) ? g_Qhi : (z == 1) ? g_Khi : (__half*)0;
    __half* outLo = (z == 0) ? g_Qlo : (z == 1) ? g_Klo : (__half*)0;

    const uint32_t sb0 = smem_u32(smh);

    auto prefetch = [&](int kt_i, int stage) {
        const int kt = kt_i * 32;
        const uint32_t sb = sb0 + (uint32_t)(stage * PROJ_STAGE * 2);
#pragma unroll
        for (int i = 0; i < 6; i++) {
            int idx = tid + i * 256;
            const __half* gp;
            uint32_t soff;
            if (idx < 512) {
                int r = idx >> 2, u = (idx & 3) * 8;
                soff = (uint32_t)(r * PSH + u);
                gp = g_Xhi + (size_t)(mbase + r) * Dx + kt + u;
            } else if (idx < 1024) {
                int v = idx - 512;
                int r = v >> 2, u = (v & 3) * 8;
                soff = (uint32_t)(128 * PSH + r * PSH + u);
                gp = g_Xlo + (size_t)(mbase + r) * Dx + kt + u;
            } else if (idx < 1280) {
                int v = idx - 1024;
                int r = v >> 2, u = (v & 3) * 8;
                soff = (uint32_t)(256 * PSH + r * PSH + u);
                gp = WTh + (size_t)(nbase + r) * Dx + kt + u;
            } else {
                int v = idx - 1280;
                int r = v >> 2, u = (v & 3) * 8;
                soff = (uint32_t)(256 * PSH + 64 * PSH + r * PSH + u);
                gp = WTl + (size_t)(nbase + r) * Dx + kt + u;
            }
            cp16(sb + soff * 2, gp);
        }
        CP_COMMIT();
    };

    // ldmatrix byte offsets within a stage
    const uint32_t offA = (uint32_t)(((wm * 32 + (lane & 15)) * PSH + (lane >> 4) * 8) * 2);
    // B x4: lanes 0-15 -> ni even tile (8 rows x 2 k-halves), 16-31 -> ni odd
    const uint32_t offB = (uint32_t)(((wn * 32 + ((lane >> 4) & 1) * 8 + (lane & 7)) * PSH
                                      + ((lane >> 3) & 1) * 8) * 2);
    const uint32_t xl_off = 128 * PSH * 2;
    const uint32_t wh_off = 256 * PSH * 2, wl_off = (256 + 64) * PSH * 2;

    float C[8][4];
#pragma unroll
    for (int p = 0; p < 8; p++)
#pragma unroll
        for (int j = 0; j < 4; j++) C[p][j] = 0.f;

    prefetch(0, 0);
    prefetch(1, 1);

    for (int it = 0; it < 16; it++) {
        const int stage = it % 3;
        if (it < 15) CP_WAIT(1); else CP_WAIT(0);
        __syncthreads();
        if (it + 2 < 16) prefetch(it + 2, (it + 2) % 3);

        const uint32_t sb = sb0 + (uint32_t)(stage * PROJ_STAGE * 2);

#pragma unroll
        for (int k16 = 0; k16 < 2; k16++) {
            const uint32_t ko = (uint32_t)(k16 * 16 * 2);
            uint32_t ah[2][4], al[2][4], bh4[2][4], bl4[2][4];
#pragma unroll
            for (int mi = 0; mi < 2; mi++) {
                uint32_t ra = sb + offA + (uint32_t)(mi * 16 * PSH * 2) + ko;
                ldm_x4(ah[mi], ra);
                ldm_x4(al[mi], ra + xl_off);
            }
#pragma unroll
            for (int nj = 0; nj < 2; nj++) {
                uint32_t rb = sb + offB + (uint32_t)(nj * 16 * PSH * 2) + ko;
                ldm_x4(bh4[nj], rb + wh_off);
                ldm_x4(bl4[nj], rb + wl_off);
            }
            // pass-major: consecutive MMAs hit distinct C tiles
#pragma unroll
            for (int ni = 0; ni < 4; ni++) {
                int nj = ni >> 1, sel = (ni & 1) * 2;
#pragma unroll
                for (int mi = 0; mi < 2; mi++)
                    mma_f16(C[mi * 4 + ni], ah[mi], bh4[nj][sel], bh4[nj][sel + 1]);
            }
#pragma unroll
            for (int ni = 0; ni < 4; ni++) {
                int nj = ni >> 1, sel = (ni & 1) * 2;
#pragma unroll
                for (int mi = 0; mi < 2; mi++)
                    mma_f16(C[mi * 4 + ni], ah[mi], bl4[nj][sel], bl4[nj][sel + 1]);
            }
#pragma unroll
            for (int ni = 0; ni < 4; ni++) {
                int nj = ni >> 1, sel = (ni & 1) * 2;
#pragma unroll
                for (int mi = 0; mi < 2; mi++)
                    mma_f16(C[mi * 4 + ni], al[mi], bh4[nj][sel], bh4[nj][sel + 1]);
            }
        }
    }

#pragma unroll
    for (int mi = 0; mi < 2; mi++) {
#pragma unroll
        for (int ni = 0; ni < 4; ni++) {
            const float* c = C[mi * 4 + ni];
            int col = nbase + (wn * 4 + ni) * 8 + 2 * tc;
            int h = col >> 6, d = col & 63;
            float b0 = bias[col], b1 = bias[col + 1];
#pragma unroll
            for (int half_ = 0; half_ < 2; half_++) {
                int r = mbase + (wm * 2 + mi) * 16 + gr + half_ * 8;
                int bb = r >> 11, l = r & 2047;
                size_t o = (((size_t)(bb * Hx + h)) * Lx + l) * DHx + d;
                float v0 = c[half_ * 2] + b0;
                float v1 = c[half_ * 2 + 1] + b1;
                *reinterpret_cast<float2*>(&out[o]) = make_float2(v0, v1);
                if (outHi) {
                    __half h0, l0, h1, l1;
                    split_h(v0, h0, l0);
                    split_h(v1, h1, l1);
                    *reinterpret_cast<__half2*>(&outHi[o]) = __halves2half2(h0, h1);
                    *reinterpret_cast<__half2*>(&outLo[o]) = __halves2half2(l0, l1);
                }
            }
        }
    }
}

// ---------------------------------------------------------------------------
// score_mma: rowmax(Q[128,64] @ K^T). 64 keys/stage, 3-stage cp.async,
// ldmatrix x4 A/B, pass-major MMA issue.
// ---------------------------------------------------------------------------
#define KSTAGE (2 * 64 * SH)
#define SCORE_SMEM ((2 * 128 * SH + 3 * KSTAGE) * 2 + 2 * 128 * 4)

__global__ __launch_bounds__(256, 2)
void score_mma_kernel()
{
    extern __shared__ __half smh[];
    __half* Qh = smh;
    __half* Ql = Qh + 128 * SH;
    __half* Kst = Ql + 128 * SH;
    float* red = reinterpret_cast<float*>(Kst + 3 * KSTAGE);

    const int tid = threadIdx.x;
    const int w = tid >> 5, lane = tid & 31;
    const int gr = lane >> 2, tc = lane & 3;
    const int wm = w >> 1, wn = w & 1;
    const int bh = blockIdx.y;
    const int qbase = blockIdx.x * 128;

    const uint32_t q_u32 = smem_u32(Qh);
    const uint32_t kst_u32 = smem_u32(Kst);

    auto prefetch_k = [&](int t, int stage) {
        const uint32_t sb = kst_u32 + (uint32_t)(stage * KSTAGE * 2);
#pragma unroll
        for (int i = 0; i < 4; i++) {
            int idx = tid + i * 256;
            int buf = idx >> 9;
            int within = idx & 511;
            int r = within >> 3;
            int u = (within & 7) * 8;
            uint32_t sa = sb + (uint32_t)((buf * 64 * SH + r * SH + u) * 2);
            const __half* gp = (buf == 0 ? g_Khi : g_Klo)
                               + ((size_t)bh * Lx + t * 64 + r) * DHx + u;
            cp16(sa, gp);
        }
        CP_COMMIT();
    };

#pragma unroll
    for (int i = 0; i < 4; i++) {
        int idx = tid + i * 256;
        int r = idx >> 3;
        int u = (idx & 7) * 8;
        size_t qs = ((size_t)bh * Lx + qbase + r) * DHx + u;
        *reinterpret_cast<uint4*>(Qh + r * SH + u) =
            *reinterpret_cast<const uint4*>(g_Qhi + qs);
        *reinterpret_cast<uint4*>(Ql + r * SH + u) =
            *reinterpret_cast<const uint4*>(g_Qlo + qs);
    }

    prefetch_k(0, 0);
    prefetch_k(1, 1);

    const uint32_t offA = (uint32_t)(((wm * 32 + (lane & 15)) * SH + (lane >> 4) * 8) * 2);
    const uint32_t offB = (uint32_t)(((wn * 32 + ((lane >> 4) & 1) * 8 + (lane & 7)) * SH
                                      + ((lane >> 3) & 1) * 8) * 2);
    const uint32_t ql_off = 128 * SH * 2;
    const uint32_t kl_off = 64 * SH * 2;

    float rm0[2], rm1[2];
#pragma unroll
    for (int mi = 0; mi < 2; mi++) { rm0[mi] = -1e30f; rm1[mi] = -1e30f; }

    for (int t = 0; t < 32; t++) {
        const int stage = t % 3;
        if (t < 31) CP_WAIT(1); else CP_WAIT(0);
        __syncthreads();
        if (t + 2 < 32) prefetch_k(t + 2, (t + 2) % 3);

        const uint32_t ksb = kst_u32 + (uint32_t)(stage * KSTAGE * 2);

        float C[8][4];
#pragma unroll
        for (int p = 0; p < 8; p++)
#pragma unroll
            for (int j = 0; j < 4; j++) C[p][j] = 0.f;

#pragma unroll
        for (int k16 = 0; k16 < 4; k16++) {
            const uint32_t ko = (uint32_t)(k16 * 16 * 2);
            uint32_t ah[2][4], al[2][4], bh4[2][4], bl4[2][4];
#pragma unroll
            for (int mi = 0; mi < 2; mi++) {
                uint32_t ra = q_u32 + offA + (uint32_t)(mi * 16 * SH * 2) + ko;
                ldm_x4(ah[mi], ra);
                ldm_x4(al[mi], ra + ql_off);
            }
#pragma unroll
            for (int nj = 0; nj < 2; nj++) {
                uint32_t rb = ksb + offB + (uint32_t)(nj * 16 * SH * 2) + ko;
                ldm_x4(bh4[nj], rb);
                ldm_x4(bl4[nj], rb + kl_off);
            }
#pragma unroll
            for (int ni = 0; ni < 4; ni++) {
                int nj = ni >> 1, sel = (ni & 1) * 2;
#pragma unroll
                for (int mi = 0; mi < 2; mi++)
                    mma_f16(C[mi * 4 + ni], ah[mi], bh4[nj][sel], bh4[nj][sel + 1]);
            }
#pragma unroll
            for (int ni = 0; ni < 4; ni++) {
                int nj = ni >> 1, sel = (ni & 1) * 2;
#pragma unroll
                for (int mi = 0; mi < 2; mi++)
                    mma_f16(C[mi * 4 + ni], ah[mi], bl4[nj][sel], bl4[nj][sel + 1]);
            }
#pragma unroll
            for (int ni = 0; ni < 4; ni++) {
                int nj = ni >> 1, sel = (ni & 1) * 2;
#pragma unroll
                for (int mi = 0; mi < 2; mi++)
                    mma_f16(C[mi * 4 + ni], al[mi], bh4[nj][sel], bh4[nj][sel + 1]);
            }
        }

#pragma unroll
        for (int mi = 0; mi < 2; mi++)
#pragma unroll
            for (int ni = 0; ni < 4; ni++) {
                const float* c = C[mi * 4 + ni];
                rm0[mi] = fmaxf(rm0[mi], fmaxf(c[0], c[1]));
                rm1[mi] = fmaxf(rm1[mi], fmaxf(c[2], c[3]));
            }
    }

#pragma unroll
    for (int mi = 0; mi < 2; mi++) {
        rm0[mi] = fmaxf(rm0[mi], __shfl_xor_sync(0xffffffffu, rm0[mi], 1));
        rm0[mi] = fmaxf(rm0[mi], __shfl_xor_sync(0xffffffffu, rm0[mi], 2));
        rm1[mi] = fmaxf(rm1[mi], __shfl_xor_sync(0xffffffffu, rm1[mi], 1));
        rm1[mi] = fmaxf(rm1[mi], __shfl_xor_sync(0xffffffffu, rm1[mi], 2));
    }
    __syncthreads();
    if (tc == 0) {
#pragma unroll
        for (int mi = 0; mi < 2; mi++) {
            int row = (wm * 2 + mi) * 16 + gr;
            red[wn * 128 + row] = rm0[mi];
            red[wn * 128 + row + 8] = rm1[mi];
        }
    }
    __syncthreads();
    if (tid < 128) {
        float m = fmaxf(red[tid], red[128 + tid]);
        g_rowmax[(size_t)bh * Lx + qbase + tid] = m;
    }
}

// ---------------------------------------------------------------------------
// K / V column sums.
// ---------------------------------------------------------------------------
__global__ void zero_sums_kernel()
{
    int i = blockIdx.x * blockDim.x + threadIdx.x;
    if (i < BHx * DHx) { g_Ksum[i] = 0.f; g_Vsum[i] = 0.f; }
}

__global__ void partial_sums_kernel()
{
    const int bh = blockIdx.x;
    const int kb = blockIdx.y * 128;
    const int tid = threadIdx.x;
    const int d = tid & 63, s = tid >> 6;
    float ks = 0.f, vs = 0.f;
    for (int k = kb + s; k < kb + 128; k += 4) {
        ks += g_K[((size_t)bh * Lx + k) * DHx + d];
        vs += g_V[((size_t)bh * Lx + k) * DHx + d];
    }
    __shared__ float red[2][256];
    red[0][tid] = ks;
    red[1][tid] = vs;
    __syncthreads();
    if (tid < 64) {
        float a = red[0][d] + red[0][d + 64] + red[0][d + 128] + red[0][d + 192];
        float b = red[1][d] + red[1][d + 64] + red[1][d + 128] + red[1][d + 192];
        atomicAdd(&g_Ksum[bh * DHx + d], a);
        atomicAdd(&g_Vsum[bh * DHx + d], b);
    }
}

// ---------------------------------------------------------------------------
// M = SCALE * (rowmax - Q.Ksum / L)
// ---------------------------------------------------------------------------
__global__ void mstat_kernel()
{
    int gidx = blockIdx.x * 256 + threadIdx.x;
    int bh = gidx >> 11;
    const float* qp = g_Q + (size_t)gidx * DHx;
    const float* ks = g_Ksum + bh * DHx;
    float dot = 0.f;
#pragma unroll
    for (int d = 0; d < DHx; d += 4) {
        float4 a = *reinterpret_cast<const float4*>(qp + d);
        float4 b = *reinterpret_cast<const float4*>(ks + d);
        dot += a.x * b.x + a.y * b.y + a.z * b.z + a.w * b.w;
    }
    g_M[gidx] = SCALEF * (g_rowmax[gidx] - dot * (1.0f / Lx));
}

// ---------------------------------------------------------------------------
// Top-38 selection per bh.
// ---------------------------------------------------------------------------
__global__ void topk_kernel()
{
    int bh = blockIdx.x;
    int tid = threadIdx.x;
    __shared__ float vals[Lx];
    __shared__ float rv[256];
    __shared__ int ri[256];
    for (int i = tid; i < Lx; i += 256) vals[i] = g_M[(size_t)bh * Lx + i];
    __syncthreads();
    for (int it = 0; it < KTOP; it++) {
        float best = -1e30f;
        int bidx = 0;
        for (int i = tid; i < Lx; i += 256) {
            float v = vals[i];
            if (v > best) { best = v; bidx = i; }
        }
        rv[tid] = best;
        ri[tid] = bidx;
        __syncthreads();
        for (int s = 128; s > 0; s >>= 1) {
            if (tid < s) {
                if (rv[tid + s] > rv[tid] ||
                    (rv[tid + s] == rv[tid] && ri[tid + s] < ri[tid])) {
                    rv[tid] = rv[tid + s];
                    ri[tid] = ri[tid + s];
                }
            }
            __syncthreads();
        }
        if (tid == 0) {
            g_top[bh * KTOP + it] = ri[0];
            vals[ri[0]] = -1e30f;
        }
        __syncthreads();
    }
}

// ---------------------------------------------------------------------------
// Sparse attention, 4 queries per block, quarter-warp QK (exact fp32).
// ---------------------------------------------------------------------------
__global__ __launch_bounds__(256)
void sparse_attn_kernel()
{
    const int bh = blockIdx.y;
    const int tid = threadIdx.x;
    const int warp = tid >> 5, lane = tid & 31;
    const int qq = lane >> 3;
    const int l8 = lane & 7;

    __shared__ float sc[4][Lx];
    __shared__ float qrow[4][DHx];
    __shared__ float red[256];
    __shared__ float red2[4][256];

    int qidx[4];
    bool valid[4];
#pragma unroll
    for (int s = 0; s < 4; s++) {
        int i = blockIdx.x + NQB * s;
        valid[s] = (i < KTOP);
        qidx[s] = valid[s] ? g_top[bh * KTOP + i] : 0;
    }

    if (tid < 256) {
        int s = tid >> 6, d = tid & 63;
        qrow[s][d] = valid[s] ? g_Q[((size_t)bh * Lx + qidx[s]) * DHx + d] : 0.f;
    }
    __syncthreads();

    float4 qf[4][2];
#pragma unroll
    for (int s = 0; s < 4; s++) {
        qf[s][0] = *reinterpret_cast<const float4*>(&qrow[s][l8 * 8]);
        qf[s][1] = *reinterpret_cast<const float4*>(&qrow[s][l8 * 8 + 4]);
    }

    for (int it = 0; it < Lx / 32; it++) {
        int k = it * 32 + warp * 4 + qq;
        const float* kr = g_K + ((size_t)bh * Lx + k) * DHx;
        float4 a = *reinterpret_cast<const float4*>(kr + l8 * 8);
        float4 b = *reinterpret_cast<const float4*>(kr + l8 * 8 + 4);
        float d0, d1, d2, d3;
        d0 = a.x*qf[0][0].x + a.y*qf[0][0].y + a.z*qf[0][0].z + a.w*qf[0][0].w
           + b.x*qf[0][1].x + b.y*qf[0][1].y + b.z*qf[0][1].z + b.w*qf[0][1].w;
        d1 = a.x*qf[1][0].x + a.y*qf[1][0].y + a.z*qf[1][0].z + a.w*qf[1][0].w
           + b.x*qf[1][1].x + b.y*qf[1][1].y + b.z*qf[1][1].z + b.w*qf[1][1].w;
        d2 = a.x*qf[2][0].x + a.y*qf[2][0].y + a.z*qf[2][0].z + a.w*qf[2][0].w
           + b.x*qf[2][1].x + b.y*qf[2][1].y + b.z*qf[2][1].z + b.w*qf[2][1].w;
        d3 = a.x*qf[3][0].x + a.y*qf[3][0].y + a.z*qf[3][0].z + a.w*qf[3][0].w
           + b.x*qf[3][1].x + b.y*qf[3][1].y + b.z*qf[3][1].z + b.w*qf[3][1].w;
#pragma unroll
        for (int o = 4; o > 0; o >>= 1) {
            d0 += __shfl_xor_sync(0xffffffffu, d0, o);
            d1 += __shfl_xor_sync(0xffffffffu, d1, o);
            d2 += __shfl_xor_sync(0xffffffffu, d2, o);
            d3 += __shfl_xor_sync(0xffffffffu, d3, o);
        }
        if (l8 == 0) {
            sc[0][k] = d0 * SCALEF;
            sc[1][k] = d1 * SCALEF;
            sc[2][k] = d2 * SCALEF;
            sc[3][k] = d3 * SCALEF;
        }
    }
    __syncthreads();

    float inv[4];
#pragma unroll 1
    for (int s = 0; s < 4; s++) {
        float* scp = sc[s];
        float mx = -1e30f;
        for (int k = tid; k < Lx; k += 256) mx = fmaxf(mx, scp[k]);
        red[tid] = mx;
        __syncthreads();
        for (int st = 128; st > 0; st >>= 1) {
            if (tid < st) red[tid] = fmaxf(red[tid], red[tid + st]);
            __syncthreads();
        }
        mx = red[0];
        __syncthreads();
        float sum = 0.f;
        for (int k = tid; k < Lx; k += 256) {
            float e = __expf(scp[k] - mx);
            scp[k] = e;
            sum += e;
        }
        red[tid] = sum;
        __syncthreads();
        for (int st = 128; st > 0; st >>= 1) {
            if (tid < st) red[tid] += red[tid + st];
            __syncthreads();
        }
        inv[s] = 1.0f / red[0];
        __syncthreads();
    }

    const int d = tid & 63, s4 = tid >> 6;
    float acc[4] = {0.f, 0.f, 0.f, 0.f};
    for (int k = s4; k < Lx; k += 4) {
        float v = g_V[((size_t)bh * Lx + k) * DHx + d];
        acc[0] += sc[0][k] * v;
        acc[1] += sc[1][k] * v;
        acc[2] += sc[2][k] * v;
        acc[3] += sc[3][k] * v;
    }
#pragma unroll
    for (int s = 0; s < 4; s++) red2[s][tid] = acc[s];
    __syncthreads();
    if (tid < 64) {
        float vm = g_Vsum[bh * DHx + d] * (1.0f / Lx);
#pragma unroll
        for (int s = 0; s < 4; s++) {
            if (!valid[s]) continue;
            float c = (red2[s][d] + red2[s][d + 64] + red2[s][d + 128] + red2[s][d + 192]) * inv[s];
            int i = blockIdx.x + NQB * s;
            g_delta[((size_t)bh * KTOP + i) * DHx + d] = c - vm;
        }
    }
}

// ---------------------------------------------------------------------------
__global__ void base_kernel(const float* __restrict__ Wo, const float* __restrict__ bo)
{
    int b = blockIdx.x, j = threadIdx.x;
    float acc = bo[j];
    for (int c = 0; c < Dx; c++) {
        int h = c >> 6, d = c & 63;
        acc += g_Vsum[(b * Hx + h) * DHx + d] * (1.0f / Lx) * Wo[(size_t)c * Dx + j];
    }
    g_base[b * Dx + j] = acc;
}

__global__ void fill_kernel(float* __restrict__ out)
{
    size_t i4 = (size_t)blockIdx.x * 256 + threadIdx.x;
    int b = (int)(i4 >> 18);
    int j4 = (int)(i4 & (Dx / 4 - 1));
    *reinterpret_cast<float4*>(out + i4 * 4) =
        *reinterpret_cast<const float4*>(g_base + b * Dx + j4 * 4);
}

__global__ void scatter_kernel(const float* __restrict__ Wo, float* __restrict__ out)
{
    const int bh = blockIdx.y;
    const int i = blockIdx.x;
    const int j = threadIdx.x;
    const int b = bh >> 3, h = bh & 7;
    const int l = g_top[bh * KTOP + i];
    __shared__ float dl[DHx];
    if (j < 64) dl[j] = g_delta[((size_t)bh * KTOP + i) * DHx + j];
    __syncthreads();
    float acc = 0.f;
#pragma unroll 16
    for (int d = 0; d < 64; d++) acc += dl[d] * Wo[(size_t)(h * 64 + d) * Dx + j];
    atomicAdd(&out[((size_t)b * Lx + l) * Dx + j], acc);
}

// ---------------------------------------------------------------------------
extern "C" void kernel_launch(void* const* d_in, const int* in_sizes, int n_in,
                              void* d_out, int out_size)
{
    const float* x  = (const float*)d_in[0];
    const float* Wq = (const float*)d_in[1];
    const float* bq = (const float*)d_in[2];
    const float* Wk = (const float*)d_in[3];
    const float* bk = (const float*)d_in[4];
    const float* Wv = (const float*)d_in[5];
    const float* bv = (const float*)d_in[6];
    const float* Wo = (const float*)d_in[7];
    const float* bo = (const float*)d_in[8];
    float* out = (float*)d_out;

    (void)in_sizes; (void)n_in; (void)out_size;

    cudaFuncSetAttribute(proj_mma_kernel,
                         cudaFuncAttributeMaxDynamicSharedMemorySize, PROJ_SMEM);
    cudaFuncSetAttribute(score_mma_kernel,
                         cudaFuncAttributeMaxDynamicSharedMemorySize, SCORE_SMEM);

    prep_w_kernel<<<dim3(16, 16, 3), 256>>>(Wq, Wk, Wv);          // 0
    prep_x_kernel<<<(Bx * Lx * Dx / 4) / 256, 256>>>(x);          // 1
    zero_sums_kernel<<<(BHx * DHx + 255) / 256, 256>>>();         // 2

    dim3 pg(Dx / 64, (Bx * Lx) / 128, 3);   // (8, 64, 3)
    proj_mma_kernel<<<pg, 256, PROJ_SMEM>>>(bq, bk, bv);          // 3 <- ncu target

    partial_sums_kernel<<<dim3(BHx, 16), 256>>>();                // 4
    score_mma_kernel<<<dim3(Lx / 128, BHx), 256, SCORE_SMEM>>>(); // 5
    mstat_kernel<<<BHx * Lx / 256, 256>>>();                      // 6
    topk_kernel<<<BHx, 256>>>();                                  // 7
    sparse_attn_kernel<<<dim3(NQB, BHx), 256>>>();                // 8
    base_kernel<<<Bx, Dx>>>(Wo, bo);                              // 9
    fill_kernel<<<(Bx * Lx * Dx / 4) / 256, 256>>>(out);          // 10
    scatter_kernel<<<dim3(KTOP, BHx), Dx>>>(Wo, out);             // 11
}

// round 15
// speedup vs baseline: 1.5218x; 1.0559x over previous
#include <cuda_runtime.h>
#include <cuda_fp16.h>
#include <math.h>
#include <stdint.h>

#define Bx 4
#define Lx 2048
#define Dx 512
#define Hx 8
#define DHx 64
#define BHx 32
#define KTOP 38
#define NQB 5         // sparse_attn blocks per bh (8 queries each, 40 slots)
#define SCALEF 0.125f
#define SH 72   // score smem halves per row
#define PSH 40  // proj stage halves per row

// ---------------- scratch (device globals; no allocation allowed) ----------
__device__ float  g_Q[BHx * Lx * DHx];
__device__ float  g_K[BHx * Lx * DHx];
__device__ float  g_V[BHx * Lx * DHx];
__device__ __half g_Xhi[Bx * Lx * Dx];
__device__ __half g_Xlo[Bx * Lx * Dx];
__device__ __half g_WThi[3 * Dx * Dx];
__device__ __half g_WTlo[3 * Dx * Dx];
__device__ __half g_Qhi[BHx * Lx * DHx];
__device__ __half g_Qlo[BHx * Lx * DHx];
__device__ __half g_Khi[BHx * Lx * DHx];
__device__ __half g_Klo[BHx * Lx * DHx];
__device__ float  g_rowmax[BHx * Lx];
__device__ float  g_M[BHx * Lx];
__device__ int    g_top[BHx * KTOP];
__device__ float  g_Ksum[BHx * DHx];
__device__ float  g_Vsum[BHx * DHx];
__device__ float  g_delta[BHx * KTOP * DHx];
__device__ float  g_base[Bx * Dx];

// ---------------- helpers ----------------------------------------------------
__device__ __forceinline__ void mma_f16(float c[4], const uint32_t a[4],
                                        uint32_t b0, uint32_t b1) {
    asm volatile(
        "mma.sync.aligned.m16n8k16.row.col.f32.f16.f16.f32 "
        "{%0,%1,%2,%3}, {%4,%5,%6,%7}, {%8,%9}, {%0,%1,%2,%3};"
        : "+f"(c[0]), "+f"(c[1]), "+f"(c[2]), "+f"(c[3])
        : "r"(a[0]), "r"(a[1]), "r"(a[2]), "r"(a[3]), "r"(b0), "r"(b1));
}
__device__ __forceinline__ void ldm_x4(uint32_t r[4], uint32_t saddr) {
    asm volatile("ldmatrix.sync.aligned.m8n8.x4.shared.b16 {%0,%1,%2,%3}, [%4];"
        : "=r"(r[0]), "=r"(r[1]), "=r"(r[2]), "=r"(r[3]) : "r"(saddr));
}
__device__ __forceinline__ void split_h(float f, __half& h, __half& l) {
    h = __float2half_rn(f);
    l = __float2half_rn(f - __half2float(h));
}
__device__ __forceinline__ uint32_t smem_u32(const void* p) {
    uint32_t a;
    asm("{ .reg .u64 t; cvta.to.shared.u64 t, %1; cvt.u32.u64 %0, t; }"
        : "=r"(a) : "l"(p));
    return a;
}
__device__ __forceinline__ void cp16(uint32_t s, const void* g) {
    asm volatile("cp.async.cg.shared.global [%0], [%1], 16;" :: "r"(s), "l"(g));
}
#define CP_COMMIT() asm volatile("cp.async.commit_group;" ::: "memory")
#define CP_WAIT(N)  asm volatile("cp.async.wait_group %0;" :: "n"(N) : "memory")

// ---------------------------------------------------------------------------
// prep_w: transpose W -> WT, split hi/lo. Block (0,0,0) also zeros the sums.
// ---------------------------------------------------------------------------
__global__ void prep_w_kernel(const float* __restrict__ Wq,
                              const float* __restrict__ Wk,
                              const float* __restrict__ Wv)
{
    __shared__ float s[32][33];
    const float* W = (blockIdx.z == 0) ? Wq : (blockIdx.z == 1) ? Wk : Wv;
    __half* dh = g_WThi + (size_t)blockIdx.z * Dx * Dx;
    __half* dl = g_WTlo + (size_t)blockIdx.z * Dx * Dx;
    const int kt = blockIdx.y * 32, ct = blockIdx.x * 32;
    const int tid = threadIdx.x;

    if (blockIdx.x == 0 && blockIdx.y == 0 && blockIdx.z == 0) {
        for (int i = tid; i < BHx * DHx; i += 256) {
            g_Ksum[i] = 0.f;
            g_Vsum[i] = 0.f;
        }
    }
    {
        int r = tid >> 3, c4 = (tid & 7) * 4;
        float4 v = *reinterpret_cast<const float4*>(&W[(size_t)(kt + r) * Dx + ct + c4]);
        s[r][c4] = v.x; s[r][c4 + 1] = v.y; s[r][c4 + 2] = v.z; s[r][c4 + 3] = v.w;
    }
    __syncthreads();
    {
        int cw = tid >> 3, k4 = (tid & 7) * 4;
        size_t o = (size_t)(ct + cw) * Dx + kt + k4;
#pragma unroll
        for (int j = 0; j < 4; j += 2) {
            __half h0, l0, h1, l1;
            split_h(s[k4 + j][cw], h0, l0);
            split_h(s[k4 + j + 1][cw], h1, l1);
            *reinterpret_cast<__half2*>(&dh[o + j]) = __halves2half2(h0, h1);
            *reinterpret_cast<__half2*>(&dl[o + j]) = __halves2half2(l0, l1);
        }
    }
}

// ---------------------------------------------------------------------------
// prep_x: split x to fp16 hi/lo.
// ---------------------------------------------------------------------------
__global__ void prep_x_kernel(const float* __restrict__ X)
{
    size_t i4 = (size_t)blockIdx.x * 256 + threadIdx.x;
    float4 v = *reinterpret_cast<const float4*>(X + i4 * 4);
    __half h0, l0, h1, l1, h2, l2, h3, l3;
    split_h(v.x, h0, l0); split_h(v.y, h1, l1);
    split_h(v.z, h2, l2); split_h(v.w, h3, l3);
    size_t o = i4 * 4;
    *reinterpret_cast<__half2*>(&g_Xhi[o])     = __halves2half2(h0, h1);
    *reinterpret_cast<__half2*>(&g_Xhi[o + 2]) = __halves2half2(h2, h3);
    *reinterpret_cast<__half2*>(&g_Xlo[o])     = __halves2half2(l0, l1);
    *reinterpret_cast<__half2*>(&g_Xlo[o + 2]) = __halves2half2(l2, l3);
}

// ---------------------------------------------------------------------------
// proj_mma: Y = X @ W + b; block 128m x 64n, BK=32, 3-stage cp.async,
// ldmatrix x4 A/B, pass-major MMA issue.
// ---------------------------------------------------------------------------
#define PROJ_STAGE ((2 * 128 + 2 * 64) * PSH)
#define PROJ_SMEM  (3 * PROJ_STAGE * 2)

__global__ __launch_bounds__(256, 2)
void proj_mma_kernel(const float* __restrict__ bq, const float* __restrict__ bk,
                     const float* __restrict__ bv)
{
    extern __shared__ __half smh[];
    const int tid = threadIdx.x;
    const int w = tid >> 5, lane = tid & 31;
    const int gr = lane >> 2, tc = lane & 3;
    const int wm = w >> 1, wn = w & 1;
    const int mbase = blockIdx.y * 128;
    const int nbase = blockIdx.x * 64;
    const int z = blockIdx.z;

    const __half* WTh = g_WThi + (size_t)z * Dx * Dx;
    const __half* WTl = g_WTlo + (size_t)z * Dx * Dx;
    const float* bias = (z == 0) ? bq : (z == 1) ? bk : bv;
    float* out = (z == 0) ? g_Q : (z == 1) ? g_K : g_V;
    __half* outHi = (z == 0) ? g_Qhi : (z == 1) ? g_Khi : (__half*)0;
    __half* outLo = (z == 0) ? g_Qlo : (z == 1) ? g_Klo : (__half*)0;

    const uint32_t sb0 = smem_u32(smh);

    auto prefetch = [&](int kt_i, int stage) {
        const int kt = kt_i * 32;
        const uint32_t sb = sb0 + (uint32_t)(stage * PROJ_STAGE * 2);
#pragma unroll
        for (int i = 0; i < 6; i++) {
            int idx = tid + i * 256;
            const __half* gp;
            uint32_t soff;
            if (idx < 512) {
                int r = idx >> 2, u = (idx & 3) * 8;
                soff = (uint32_t)(r * PSH + u);
                gp = g_Xhi + (size_t)(mbase + r) * Dx + kt + u;
            } else if (idx < 1024) {
                int v = idx - 512;
                int r = v >> 2, u = (v & 3) * 8;
                soff = (uint32_t)(128 * PSH + r * PSH + u);
                gp = g_Xlo + (size_t)(mbase + r) * Dx + kt + u;
            } else if (idx < 1280) {
                int v = idx - 1024;
                int r = v >> 2, u = (v & 3) * 8;
                soff = (uint32_t)(256 * PSH + r * PSH + u);
                gp = WTh + (size_t)(nbase + r) * Dx + kt + u;
            } else {
                int v = idx - 1280;
                int r = v >> 2, u = (v & 3) * 8;
                soff = (uint32_t)(256 * PSH + 64 * PSH + r * PSH + u);
                gp = WTl + (size_t)(nbase + r) * Dx + kt + u;
            }
            cp16(sb + soff * 2, gp);
        }
        CP_COMMIT();
    };

    const uint32_t offA = (uint32_t)(((wm * 32 + (lane & 15)) * PSH + (lane >> 4) * 8) * 2);
    const uint32_t offB = (uint32_t)(((wn * 32 + ((lane >> 4) & 1) * 8 + (lane & 7)) * PSH
                                      + ((lane >> 3) & 1) * 8) * 2);
    const uint32_t xl_off = 128 * PSH * 2;
    const uint32_t wh_off = 256 * PSH * 2, wl_off = (256 + 64) * PSH * 2;

    float C[8][4];
#pragma unroll
    for (int p = 0; p < 8; p++)
#pragma unroll
        for (int j = 0; j < 4; j++) C[p][j] = 0.f;

    prefetch(0, 0);
    prefetch(1, 1);

    for (int it = 0; it < 16; it++) {
        const int stage = it % 3;
        if (it < 15) CP_WAIT(1); else CP_WAIT(0);
        __syncthreads();
        if (it + 2 < 16) prefetch(it + 2, (it + 2) % 3);

        const uint32_t sb = sb0 + (uint32_t)(stage * PROJ_STAGE * 2);

#pragma unroll
        for (int k16 = 0; k16 < 2; k16++) {
            const uint32_t ko = (uint32_t)(k16 * 16 * 2);
            uint32_t ah[2][4], al[2][4], bh4[2][4], bl4[2][4];
#pragma unroll
            for (int mi = 0; mi < 2; mi++) {
                uint32_t ra = sb + offA + (uint32_t)(mi * 16 * PSH * 2) + ko;
                ldm_x4(ah[mi], ra);
                ldm_x4(al[mi], ra + xl_off);
            }
#pragma unroll
            for (int nj = 0; nj < 2; nj++) {
                uint32_t rb = sb + offB + (uint32_t)(nj * 16 * PSH * 2) + ko;
                ldm_x4(bh4[nj], rb + wh_off);
                ldm_x4(bl4[nj], rb + wl_off);
            }
#pragma unroll
            for (int ni = 0; ni < 4; ni++) {
                int nj = ni >> 1, sel = (ni & 1) * 2;
#pragma unroll
                for (int mi = 0; mi < 2; mi++)
                    mma_f16(C[mi * 4 + ni], ah[mi], bh4[nj][sel], bh4[nj][sel + 1]);
            }
#pragma unroll
            for (int ni = 0; ni < 4; ni++) {
                int nj = ni >> 1, sel = (ni & 1) * 2;
#pragma unroll
                for (int mi = 0; mi < 2; mi++)
                    mma_f16(C[mi * 4 + ni], ah[mi], bl4[nj][sel], bl4[nj][sel + 1]);
            }
#pragma unroll
            for (int ni = 0; ni < 4; ni++) {
                int nj = ni >> 1, sel = (ni & 1) * 2;
#pragma unroll
                for (int mi = 0; mi < 2; mi++)
                    mma_f16(C[mi * 4 + ni], al[mi], bh4[nj][sel], bh4[nj][sel + 1]);
            }
        }
    }

#pragma unroll
    for (int mi = 0; mi < 2; mi++) {
#pragma unroll
        for (int ni = 0; ni < 4; ni++) {
            const float* c = C[mi * 4 + ni];
            int col = nbase + (wn * 4 + ni) * 8 + 2 * tc;
            int h = col >> 6, d = col & 63;
            float b0 = bias[col], b1 = bias[col + 1];
#pragma unroll
            for (int half_ = 0; half_ < 2; half_++) {
                int r = mbase + (wm * 2 + mi) * 16 + gr + half_ * 8;
                int bb = r >> 11, l = r & 2047;
                size_t o = (((size_t)(bb * Hx + h)) * Lx + l) * DHx + d;
                float v0 = c[half_ * 2] + b0;
                float v1 = c[half_ * 2 + 1] + b1;
                *reinterpret_cast<float2*>(&out[o]) = make_float2(v0, v1);
                if (outHi) {
                    __half h0, l0, h1, l1;
                    split_h(v0, h0, l0);
                    split_h(v1, h1, l1);
                    *reinterpret_cast<__half2*>(&outHi[o]) = __halves2half2(h0, h1);
                    *reinterpret_cast<__half2*>(&outLo[o]) = __halves2half2(l0, l1);
                }
            }
        }
    }
}

// ---------------------------------------------------------------------------
// score_mma: rowmax(Q[128,64] @ K^T). 64 keys/stage, 3-stage cp.async,
// ldmatrix x4 A/B, pass-major MMA issue.
// ---------------------------------------------------------------------------
#define KSTAGE (2 * 64 * SH)
#define SCORE_SMEM ((2 * 128 * SH + 3 * KSTAGE) * 2 + 2 * 128 * 4)

__global__ __launch_bounds__(256, 2)
void score_mma_kernel()
{
    extern __shared__ __half smh[];
    __half* Qh = smh;
    __half* Ql = Qh + 128 * SH;
    __half* Kst = Ql + 128 * SH;
    float* red = reinterpret_cast<float*>(Kst + 3 * KSTAGE);

    const int tid = threadIdx.x;
    const int w = tid >> 5, lane = tid & 31;
    const int gr = lane >> 2, tc = lane & 3;
    const int wm = w >> 1, wn = w & 1;
    const int bh = blockIdx.y;
    const int qbase = blockIdx.x * 128;

    const uint32_t q_u32 = smem_u32(Qh);
    const uint32_t kst_u32 = smem_u32(Kst);

    auto prefetch_k = [&](int t, int stage) {
        const uint32_t sb = kst_u32 + (uint32_t)(stage * KSTAGE * 2);
#pragma unroll
        for (int i = 0; i < 4; i++) {
            int idx = tid + i * 256;
            int buf = idx >> 9;
            int within = idx & 511;
            int r = within >> 3;
            int u = (within & 7) * 8;
            uint32_t sa = sb + (uint32_t)((buf * 64 * SH + r * SH + u) * 2);
            const __half* gp = (buf == 0 ? g_Khi : g_Klo)
                               + ((size_t)bh * Lx + t * 64 + r) * DHx + u;
            cp16(sa, gp);
        }
        CP_COMMIT();
    };

#pragma unroll
    for (int i = 0; i < 4; i++) {
        int idx = tid + i * 256;
        int r = idx >> 3;
        int u = (idx & 7) * 8;
        size_t qs = ((size_t)bh * Lx + qbase + r) * DHx + u;
        *reinterpret_cast<uint4*>(Qh + r * SH + u) =
            *reinterpret_cast<const uint4*>(g_Qhi + qs);
        *reinterpret_cast<uint4*>(Ql + r * SH + u) =
            *reinterpret_cast<const uint4*>(g_Qlo + qs);
    }

    prefetch_k(0, 0);
    prefetch_k(1, 1);

    const uint32_t offA = (uint32_t)(((wm * 32 + (lane & 15)) * SH + (lane >> 4) * 8) * 2);
    const uint32_t offB = (uint32_t)(((wn * 32 + ((lane >> 4) & 1) * 8 + (lane & 7)) * SH
                                      + ((lane >> 3) & 1) * 8) * 2);
    const uint32_t ql_off = 128 * SH * 2;
    const uint32_t kl_off = 64 * SH * 2;

    float rm0[2], rm1[2];
#pragma unroll
    for (int mi = 0; mi < 2; mi++) { rm0[mi] = -1e30f; rm1[mi] = -1e30f; }

    for (int t = 0; t < 32; t++) {
        const int stage = t % 3;
        if (t < 31) CP_WAIT(1); else CP_WAIT(0);
        __syncthreads();
        if (t + 2 < 32) prefetch_k(t + 2, (t + 2) % 3);

        const uint32_t ksb = kst_u32 + (uint32_t)(stage * KSTAGE * 2);

        float C[8][4];
#pragma unroll
        for (int p = 0; p < 8; p++)
#pragma unroll
            for (int j = 0; j < 4; j++) C[p][j] = 0.f;

#pragma unroll
        for (int k16 = 0; k16 < 4; k16++) {
            const uint32_t ko = (uint32_t)(k16 * 16 * 2);
            uint32_t ah[2][4], al[2][4], bh4[2][4], bl4[2][4];
#pragma unroll
            for (int mi = 0; mi < 2; mi++) {
                uint32_t ra = q_u32 + offA + (uint32_t)(mi * 16 * SH * 2) + ko;
                ldm_x4(ah[mi], ra);
                ldm_x4(al[mi], ra + ql_off);
            }
#pragma unroll
            for (int nj = 0; nj < 2; nj++) {
                uint32_t rb = ksb + offB + (uint32_t)(nj * 16 * SH * 2) + ko;
                ldm_x4(bh4[nj], rb);
                ldm_x4(bl4[nj], rb + kl_off);
            }
#pragma unroll
            for (int ni = 0; ni < 4; ni++) {
                int nj = ni >> 1, sel = (ni & 1) * 2;
#pragma unroll
                for (int mi = 0; mi < 2; mi++)
                    mma_f16(C[mi * 4 + ni], ah[mi], bh4[nj][sel], bh4[nj][sel + 1]);
            }
#pragma unroll
            for (int ni = 0; ni < 4; ni++) {
                int nj = ni >> 1, sel = (ni & 1) * 2;
#pragma unroll
                for (int mi = 0; mi < 2; mi++)
                    mma_f16(C[mi * 4 + ni], ah[mi], bl4[nj][sel], bl4[nj][sel + 1]);
            }
#pragma unroll
            for (int ni = 0; ni < 4; ni++) {
                int nj = ni >> 1, sel = (ni & 1) * 2;
#pragma unroll
                for (int mi = 0; mi < 2; mi++)
                    mma_f16(C[mi * 4 + ni], al[mi], bh4[nj][sel], bh4[nj][sel + 1]);
            }
        }

#pragma unroll
        for (int mi = 0; mi < 2; mi++)
#pragma unroll
            for (int ni = 0; ni < 4; ni++) {
                const float* c = C[mi * 4 + ni];
                rm0[mi] = fmaxf(rm0[mi], fmaxf(c[0], c[1]));
                rm1[mi] = fmaxf(rm1[mi], fmaxf(c[2], c[3]));
            }
    }

#pragma unroll
    for (int mi = 0; mi < 2; mi++) {
        rm0[mi] = fmaxf(rm0[mi], __shfl_xor_sync(0xffffffffu, rm0[mi], 1));
        rm0[mi] = fmaxf(rm0[mi], __shfl_xor_sync(0xffffffffu, rm0[mi], 2));
        rm1[mi] = fmaxf(rm1[mi], __shfl_xor_sync(0xffffffffu, rm1[mi], 1));
        rm1[mi] = fmaxf(rm1[mi], __shfl_xor_sync(0xffffffffu, rm1[mi], 2));
    }
    __syncthreads();
    if (tc == 0) {
#pragma unroll
        for (int mi = 0; mi < 2; mi++) {
            int row = (wm * 2 + mi) * 16 + gr;
            red[wn * 128 + row] = rm0[mi];
            red[wn * 128 + row + 8] = rm1[mi];
        }
    }
    __syncthreads();
    if (tid < 128) {
        float m = fmaxf(red[tid], red[128 + tid]);
        g_rowmax[(size_t)bh * Lx + qbase + tid] = m;
    }
}

// ---------------------------------------------------------------------------
// K / V column sums (zeroed in prep_w).
// ---------------------------------------------------------------------------
__global__ void partial_sums_kernel()
{
    const int bh = blockIdx.x;
    const int kb = blockIdx.y * 128;
    const int tid = threadIdx.x;
    const int d = tid & 63, s = tid >> 6;
    float ks = 0.f, vs = 0.f;
    for (int k = kb + s; k < kb + 128; k += 4) {
        ks += g_K[((size_t)bh * Lx + k) * DHx + d];
        vs += g_V[((size_t)bh * Lx + k) * DHx + d];
    }
    __shared__ float red[2][256];
    red[0][tid] = ks;
    red[1][tid] = vs;
    __syncthreads();
    if (tid < 64) {
        float a = red[0][d] + red[0][d + 64] + red[0][d + 128] + red[0][d + 192];
        float b = red[1][d] + red[1][d + 64] + red[1][d + 128] + red[1][d + 192];
        atomicAdd(&g_Ksum[bh * DHx + d], a);
        atomicAdd(&g_Vsum[bh * DHx + d], b);
    }
}

// ---------------------------------------------------------------------------
// M = SCALE * (rowmax - Q.Ksum / L)
// ---------------------------------------------------------------------------
__global__ void mstat_kernel()
{
    int gidx = blockIdx.x * 256 + threadIdx.x;
    int bh = gidx >> 11;
    const float* qp = g_Q + (size_t)gidx * DHx;
    const float* ks = g_Ksum + bh * DHx;
    float dot = 0.f;
#pragma unroll
    for (int d = 0; d < DHx; d += 4) {
        float4 a = *reinterpret_cast<const float4*>(qp + d);
        float4 b = *reinterpret_cast<const float4*>(ks + d);
        dot += a.x * b.x + a.y * b.y + a.z * b.z + a.w * b.w;
    }
    g_M[gidx] = SCALEF * (g_rowmax[gidx] - dot * (1.0f / Lx));
}

// ---------------------------------------------------------------------------
// Top-38 per bh: packed (value, ~index) uint64 keys, shfl-reduce,
// 2 barriers per iteration. Tiebreak = lowest index (via ~idx in low word).
// ---------------------------------------------------------------------------
__global__ void topk_kernel()
{
    const int bh = blockIdx.x;
    const int tid = threadIdx.x;
    const int lane = tid & 31, warp = tid >> 5;
    __shared__ float vals[Lx];
    __shared__ unsigned long long wred[8];

    for (int i = tid; i < Lx; i += 256) vals[i] = g_M[(size_t)bh * Lx + i];
    __syncthreads();

    for (int it = 0; it < KTOP; it++) {
        unsigned long long best = 0ull;
#pragma unroll
        for (int j = 0; j < Lx / 256; j++) {
            int i = tid + j * 256;
            uint32_t fb = __float_as_uint(vals[i]);
            fb = (fb & 0x80000000u) ? ~fb : (fb | 0x80000000u);
            unsigned long long key =
                ((unsigned long long)fb << 32) | (uint32_t)(~i);
            if (key > best) best = key;
        }
#pragma unroll
        for (int o = 16; o > 0; o >>= 1) {
            unsigned long long other = __shfl_xor_sync(0xffffffffu, best, o);
            if (other > best) best = other;
        }
        if (lane == 0) wred[warp] = best;
        __syncthreads();
        if (tid == 0) {
            unsigned long long b = wred[0];
#pragma unroll
            for (int v = 1; v < 8; v++) if (wred[v] > b) b = wred[v];
            int idx = (int)(~(uint32_t)b);
            g_top[bh * KTOP + it] = idx;
            vals[idx] = -1e30f;
        }
        __syncthreads();
    }
}

// ---------------------------------------------------------------------------
// Sparse attention, 8 queries per block, quarter-warp QK, warp-per-query
// softmax (exact fp32). grid (NQB, BHx); slots i = blockIdx.x + NQB*s, s<8.
// ---------------------------------------------------------------------------
#define SPARSE_SMEM ((8 * Lx + 8 * DHx + 8 + 8 * 256) * 4)

__global__ __launch_bounds__(256)
void sparse_attn_kernel()
{
    extern __shared__ float sm[];
    float (*sc)[Lx]   = reinterpret_cast<float(*)[Lx]>(sm);
    float (*qrow)[DHx] = reinterpret_cast<float(*)[DHx]>(sm + 8 * Lx);
    float* invs = sm + 8 * Lx + 8 * DHx;                 // 8
    float (*red2)[256] = reinterpret_cast<float(*)[256]>(invs + 8);

    const int bh = blockIdx.y;
    const int tid = threadIdx.x;
    const int warp = tid >> 5, lane = tid & 31;
    const int qq = lane >> 3;
    const int l8 = lane & 7;

    // load 8 query rows (zeros for invalid slots)
    for (int e = tid; e < 8 * DHx; e += 256) {
        int s = e >> 6, d = e & 63;
        int i = blockIdx.x + NQB * s;
        qrow[s][d] = (i < KTOP)
            ? g_Q[((size_t)bh * Lx + g_top[bh * KTOP + i]) * DHx + d] : 0.f;
    }
    __syncthreads();

    float4 qf[8][2];
#pragma unroll
    for (int s = 0; s < 8; s++) {
        qf[s][0] = *reinterpret_cast<const float4*>(&qrow[s][l8 * 8]);
        qf[s][1] = *reinterpret_cast<const float4*>(&qrow[s][l8 * 8 + 4]);
    }

    // QK: each warp-iteration covers 4 keys (one per quarter), 8 dots each
    for (int it = 0; it < Lx / 32; it++) {
        int k = it * 32 + warp * 4 + qq;
        const float* kr = g_K + ((size_t)bh * Lx + k) * DHx;
        float4 a = *reinterpret_cast<const float4*>(kr + l8 * 8);
        float4 b = *reinterpret_cast<const float4*>(kr + l8 * 8 + 4);
        float dts[8];
#pragma unroll
        for (int s = 0; s < 8; s++) {
            dts[s] = a.x*qf[s][0].x + a.y*qf[s][0].y + a.z*qf[s][0].z + a.w*qf[s][0].w
                   + b.x*qf[s][1].x + b.y*qf[s][1].y + b.z*qf[s][1].z + b.w*qf[s][1].w;
        }
#pragma unroll
        for (int o = 4; o > 0; o >>= 1)
#pragma unroll
            for (int s = 0; s < 8; s++)
                dts[s] += __shfl_xor_sync(0xffffffffu, dts[s], o);
        if (l8 == 0) {
#pragma unroll
            for (int s = 0; s < 8; s++) sc[s][k] = dts[s] * SCALEF;
        }
    }
    __syncthreads();

    // softmax: warp w owns query w (no block barriers inside)
    {
        float* scp = sc[warp];
        float mx = -1e30f;
        for (int k = lane; k < Lx; k += 32) mx = fmaxf(mx, scp[k]);
#pragma unroll
        for (int o = 16; o > 0; o >>= 1)
            mx = fmaxf(mx, __shfl_xor_sync(0xffffffffu, mx, o));
        float sum = 0.f;
        for (int k = lane; k < Lx; k += 32) {
            float e = __expf(scp[k] - mx);
            scp[k] = e;
            sum += e;
        }
#pragma unroll
        for (int o = 16; o > 0; o >>= 1)
            sum += __shfl_xor_sync(0xffffffffu, sum, o);
        if (lane == 0) invs[warp] = 1.0f / sum;
    }
    __syncthreads();

    // PV: each V load feeds 8 queries
    const int d = tid & 63, s4 = tid >> 6;
    float acc[8] = {0.f, 0.f, 0.f, 0.f, 0.f, 0.f, 0.f, 0.f};
    for (int k = s4; k < Lx; k += 4) {
        float v = g_V[((size_t)bh * Lx + k) * DHx + d];
#pragma unroll
        for (int s = 0; s < 8; s++) acc[s] += sc[s][k] * v;
    }
#pragma unroll
    for (int s = 0; s < 8; s++) red2[s][tid] = acc[s];
    __syncthreads();
    if (tid < 64) {
        float vm = g_Vsum[bh * DHx + d] * (1.0f / Lx);
#pragma unroll
        for (int s = 0; s < 8; s++) {
            int i = blockIdx.x + NQB * s;
            if (i >= KTOP) continue;
            float c = (red2[s][d] + red2[s][d + 64] + red2[s][d + 128] + red2[s][d + 192])
                      * invs[s];
            g_delta[((size_t)bh * KTOP + i) * DHx + d] = c - vm;
        }
    }
}

// ---------------------------------------------------------------------------
__global__ void base_kernel(const float* __restrict__ Wo, const float* __restrict__ bo)
{
    int b = blockIdx.x, j = threadIdx.x;
    float acc = bo[j];
    for (int c = 0; c < Dx; c++) {
        int h = c >> 6, d = c & 63;
        acc += g_Vsum[(b * Hx + h) * DHx + d] * (1.0f / Lx) * Wo[(size_t)c * Dx + j];
    }
    g_base[b * Dx + j] = acc;
}

__global__ void fill_kernel(float* __restrict__ out)
{
    size_t i4 = (size_t)blockIdx.x * 256 + threadIdx.x;
    int b = (int)(i4 >> 18);
    int j4 = (int)(i4 & (Dx / 4 - 1));
    *reinterpret_cast<float4*>(out + i4 * 4) =
        *reinterpret_cast<const float4*>(g_base + b * Dx + j4 * 4);
}

__global__ void scatter_kernel(const float* __restrict__ Wo, float* __restrict__ out)
{
    const int bh = blockIdx.y;
    const int i = blockIdx.x;
    const int j = threadIdx.x;
    const int b = bh >> 3, h = bh & 7;
    const int l = g_top[bh * KTOP + i];
    __shared__ float dl[DHx];
    if (j < 64) dl[j] = g_delta[((size_t)bh * KTOP + i) * DHx + j];
    __syncthreads();
    float acc = 0.f;
#pragma unroll 16
    for (int d = 0; d < 64; d++) acc += dl[d] * Wo[(size_t)(h * 64 + d) * Dx + j];
    atomicAdd(&out[((size_t)b * Lx + l) * Dx + j], acc);
}

// ---------------------------------------------------------------------------
extern "C" void kernel_launch(void* const* d_in, const int* in_sizes, int n_in,
                              void* d_out, int out_size)
{
    const float* x  = (const float*)d_in[0];
    const float* Wq = (const float*)d_in[1];
    const float* bq = (const float*)d_in[2];
    const float* Wk = (const float*)d_in[3];
    const float* bk = (const float*)d_in[4];
    const float* Wv = (const float*)d_in[5];
    const float* bv = (const float*)d_in[6];
    const float* Wo = (const float*)d_in[7];
    const float* bo = (const float*)d_in[8];
    float* out = (float*)d_out;

    (void)in_sizes; (void)n_in; (void)out_size;

    cudaFuncSetAttribute(proj_mma_kernel,
                         cudaFuncAttributeMaxDynamicSharedMemorySize, PROJ_SMEM);
    cudaFuncSetAttribute(score_mma_kernel,
                         cudaFuncAttributeMaxDynamicSharedMemorySize, SCORE_SMEM);
    cudaFuncSetAttribute(sparse_attn_kernel,
                         cudaFuncAttributeMaxDynamicSharedMemorySize, SPARSE_SMEM);

    prep_w_kernel<<<dim3(16, 16, 3), 256>>>(Wq, Wk, Wv);          // 0 (+ zero sums)
    prep_x_kernel<<<(Bx * Lx * Dx / 4) / 256, 256>>>(x);          // 1

    dim3 pg(Dx / 64, (Bx * Lx) / 128, 3);   // (8, 64, 3)
    proj_mma_kernel<<<pg, 256, PROJ_SMEM>>>(bq, bk, bv);          // 2

    score_mma_kernel<<<dim3(Lx / 128, BHx), 256, SCORE_SMEM>>>(); // 3 <- ncu target

    partial_sums_kernel<<<dim3(BHx, 16), 256>>>();                // 4
    mstat_kernel<<<BHx * Lx / 256, 256>>>();                      // 5
    topk_kernel<<<BHx, 256>>>();                                  // 6
    sparse_attn_kernel<<<dim3(NQB, BHx), 256, SPARSE_SMEM>>>();   // 7
    base_kernel<<<Bx, Dx>>>(Wo, bo);                              // 8
    fill_kernel<<<(Bx * Lx * Dx / 4) / 256, 256>>>(out);          // 9
    scatter_kernel<<<dim3(KTOP, BHx), Dx>>>(Wo, out);             // 10
}

// round 16
// speedup vs baseline: 1.5773x; 1.0365x over previous
#include <cuda_runtime.h>
#include <cuda_fp16.h>
#include <math.h>
#include <stdint.h>

#define Bx 4
#define Lx 2048
#define Dx 512
#define Hx 8
#define DHx 64
#define BHx 32
#define KTOP 38
#define NQB 5         // sparse_attn blocks per bh (8 queries each, 40 slots)
#define SCALEF 0.125f
#define SH 72   // smem halves per row (both MMA kernels)

// ---------------- scratch (device globals; no allocation allowed) ----------
__device__ float  g_Q[BHx * Lx * DHx];
__device__ float  g_K[BHx * Lx * DHx];
__device__ float  g_V[BHx * Lx * DHx];
__device__ __half g_Xhi[Bx * Lx * Dx];
__device__ __half g_Xlo[Bx * Lx * Dx];
__device__ __half g_WThi[3 * Dx * Dx];
__device__ __half g_WTlo[3 * Dx * Dx];
__device__ __half g_Qhi[BHx * Lx * DHx];
__device__ __half g_Qlo[BHx * Lx * DHx];
__device__ __half g_Khi[BHx * Lx * DHx];
__device__ __half g_Klo[BHx * Lx * DHx];
__device__ float  g_rowmax[BHx * Lx];
__device__ float  g_M[BHx * Lx];
__device__ int    g_top[BHx * KTOP];
__device__ float  g_Ksum[BHx * DHx];
__device__ float  g_Vsum[BHx * DHx];
__device__ float  g_delta[BHx * KTOP * DHx];
__device__ float  g_base[Bx * Dx];

// ---------------- helpers ----------------------------------------------------
__device__ __forceinline__ void mma_f16(float c[4], const uint32_t a[4],
                                        uint32_t b0, uint32_t b1) {
    asm volatile(
        "mma.sync.aligned.m16n8k16.row.col.f32.f16.f16.f32 "
        "{%0,%1,%2,%3}, {%4,%5,%6,%7}, {%8,%9}, {%0,%1,%2,%3};"
        : "+f"(c[0]), "+f"(c[1]), "+f"(c[2]), "+f"(c[3])
        : "r"(a[0]), "r"(a[1]), "r"(a[2]), "r"(a[3]), "r"(b0), "r"(b1));
}
__device__ __forceinline__ void ldm_x4(uint32_t r[4], uint32_t saddr) {
    asm volatile("ldmatrix.sync.aligned.m8n8.x4.shared.b16 {%0,%1,%2,%3}, [%4];"
        : "=r"(r[0]), "=r"(r[1]), "=r"(r[2]), "=r"(r[3]) : "r"(saddr));
}
__device__ __forceinline__ void split_h(float f, __half& h, __half& l) {
    h = __float2half_rn(f);
    l = __float2half_rn(f - __half2float(h));
}
__device__ __forceinline__ uint32_t smem_u32(const void* p) {
    uint32_t a;
    asm("{ .reg .u64 t; cvta.to.shared.u64 t, %1; cvt.u32.u64 %0, t; }"
        : "=r"(a) : "l"(p));
    return a;
}
__device__ __forceinline__ void cp16(uint32_t s, const void* g) {
    asm volatile("cp.async.cg.shared.global [%0], [%1], 16;" :: "r"(s), "l"(g));
}
#define CP_COMMIT() asm volatile("cp.async.commit_group;" ::: "memory")
#define CP_WAIT(N)  asm volatile("cp.async.wait_group %0;" :: "n"(N) : "memory")

// ---------------------------------------------------------------------------
// prep_w: transpose W -> WT, split hi/lo. Block (0,0,0) also zeros the sums.
// ---------------------------------------------------------------------------
__global__ void prep_w_kernel(const float* __restrict__ Wq,
                              const float* __restrict__ Wk,
                              const float* __restrict__ Wv)
{
    __shared__ float s[32][33];
    const float* W = (blockIdx.z == 0) ? Wq : (blockIdx.z == 1) ? Wk : Wv;
    __half* dh = g_WThi + (size_t)blockIdx.z * Dx * Dx;
    __half* dl = g_WTlo + (size_t)blockIdx.z * Dx * Dx;
    const int kt = blockIdx.y * 32, ct = blockIdx.x * 32;
    const int tid = threadIdx.x;

    if (blockIdx.x == 0 && blockIdx.y == 0 && blockIdx.z == 0) {
        for (int i = tid; i < BHx * DHx; i += 256) {
            g_Ksum[i] = 0.f;
            g_Vsum[i] = 0.f;
        }
    }
    {
        int r = tid >> 3, c4 = (tid & 7) * 4;
        float4 v = *reinterpret_cast<const float4*>(&W[(size_t)(kt + r) * Dx + ct + c4]);
        s[r][c4] = v.x; s[r][c4 + 1] = v.y; s[r][c4 + 2] = v.z; s[r][c4 + 3] = v.w;
    }
    __syncthreads();
    {
        int cw = tid >> 3, k4 = (tid & 7) * 4;
        size_t o = (size_t)(ct + cw) * Dx + kt + k4;
#pragma unroll
        for (int j = 0; j < 4; j += 2) {
            __half h0, l0, h1, l1;
            split_h(s[k4 + j][cw], h0, l0);
            split_h(s[k4 + j + 1][cw], h1, l1);
            *reinterpret_cast<__half2*>(&dh[o + j]) = __halves2half2(h0, h1);
            *reinterpret_cast<__half2*>(&dl[o + j]) = __halves2half2(l0, l1);
        }
    }
}

// ---------------------------------------------------------------------------
// prep_x: split x to fp16 hi/lo. Two half-grid launches (keeps proj at idx 3).
// ---------------------------------------------------------------------------
__global__ void prep_x_kernel(const float* __restrict__ X, int base4)
{
    size_t i4 = (size_t)base4 + (size_t)blockIdx.x * 256 + threadIdx.x;
    float4 v = *reinterpret_cast<const float4*>(X + i4 * 4);
    __half h0, l0, h1, l1, h2, l2, h3, l3;
    split_h(v.x, h0, l0); split_h(v.y, h1, l1);
    split_h(v.z, h2, l2); split_h(v.w, h3, l3);
    size_t o = i4 * 4;
    *reinterpret_cast<__half2*>(&g_Xhi[o])     = __halves2half2(h0, h1);
    *reinterpret_cast<__half2*>(&g_Xhi[o + 2]) = __halves2half2(h2, h3);
    *reinterpret_cast<__half2*>(&g_Xlo[o])     = __halves2half2(l0, l1);
    *reinterpret_cast<__half2*>(&g_Xlo[o + 2]) = __halves2half2(l2, l3);
}

// ---------------------------------------------------------------------------
// proj_mma: Y = X @ W + b; block 128m x 64n, BK=64, 2-stage cp.async,
// 96 MMAs per barrier (score-like overhead ratio), ldmatrix x4, pass-major.
// Stage layout (halves): Xh[128*SH] | Xl[128*SH] | Wh[64*SH] | Wl[64*SH]
// ---------------------------------------------------------------------------
#define PROJ_STAGE ((2 * 128 + 2 * 64) * SH)       // 27648 halves
#define PROJ_SMEM  (2 * PROJ_STAGE * 2)            // 110592 B

__global__ __launch_bounds__(256, 2)
void proj_mma_kernel(const float* __restrict__ bq, const float* __restrict__ bk,
                     const float* __restrict__ bv)
{
    extern __shared__ __half smh[];
    const int tid = threadIdx.x;
    const int w = tid >> 5, lane = tid & 31;
    const int gr = lane >> 2, tc = lane & 3;
    const int wm = w >> 1, wn = w & 1;
    const int mbase = blockIdx.y * 128;
    const int nbase = blockIdx.x * 64;
    const int z = blockIdx.z;

    const __half* WTh = g_WThi + (size_t)z * Dx * Dx;
    const __half* WTl = g_WTlo + (size_t)z * Dx * Dx;
    const float* bias = (z == 0) ? bq : (z == 1) ? bk : bv;
    float* out = (z == 0) ? g_Q : (z == 1) ? g_K : g_V;
    __half* outHi = (z == 0) ? g_Qhi : (z == 1) ? g_Khi : (__half*)0;
    __half* outLo = (z == 0) ? g_Qlo : (z == 1) ? g_Klo : (__half*)0;

    const uint32_t sb0 = smem_u32(smh);

    // 3072 cp16 chunks per stage: Xh 1024, Xl 1024, Wh 512, Wl 512
    auto prefetch = [&](int kt_i, int stage) {
        const int kt = kt_i * 64;
        const uint32_t sb = sb0 + (uint32_t)(stage * PROJ_STAGE * 2);
#pragma unroll
        for (int i = 0; i < 12; i++) {
            int idx = tid + i * 256;
            const __half* gp;
            uint32_t soff;
            if (idx < 1024) {
                int r = idx >> 3, u = (idx & 7) * 8;
                soff = (uint32_t)(r * SH + u);
                gp = g_Xhi + (size_t)(mbase + r) * Dx + kt + u;
            } else if (idx < 2048) {
                int v = idx - 1024;
                int r = v >> 3, u = (v & 7) * 8;
                soff = (uint32_t)(128 * SH + r * SH + u);
                gp = g_Xlo + (size_t)(mbase + r) * Dx + kt + u;
            } else if (idx < 2560) {
                int v = idx - 2048;
                int r = v >> 3, u = (v & 7) * 8;
                soff = (uint32_t)(256 * SH + r * SH + u);
                gp = WTh + (size_t)(nbase + r) * Dx + kt + u;
            } else {
                int v = idx - 2560;
                int r = v >> 3, u = (v & 7) * 8;
                soff = (uint32_t)((256 + 64) * SH + r * SH + u);
                gp = WTl + (size_t)(nbase + r) * Dx + kt + u;
            }
            cp16(sb + soff * 2, gp);
        }
        CP_COMMIT();
    };

    const uint32_t offA = (uint32_t)(((wm * 32 + (lane & 15)) * SH + (lane >> 4) * 8) * 2);
    const uint32_t offB = (uint32_t)(((wn * 32 + ((lane >> 4) & 1) * 8 + (lane & 7)) * SH
                                      + ((lane >> 3) & 1) * 8) * 2);
    const uint32_t xl_off = 128 * SH * 2;
    const uint32_t wh_off = 256 * SH * 2, wl_off = (256 + 64) * SH * 2;

    float C[8][4];
#pragma unroll
    for (int p = 0; p < 8; p++)
#pragma unroll
        for (int j = 0; j < 4; j++) C[p][j] = 0.f;

    prefetch(0, 0);

    for (int it = 0; it < 8; it++) {
        const int stage = it & 1;
        CP_WAIT(0);
        __syncthreads();
        if (it < 7) prefetch(it + 1, stage ^ 1);

        const uint32_t sb = sb0 + (uint32_t)(stage * PROJ_STAGE * 2);

#pragma unroll
        for (int k16 = 0; k16 < 4; k16++) {
            const uint32_t ko = (uint32_t)(k16 * 16 * 2);
            uint32_t ah[2][4], al[2][4], bh4[2][4], bl4[2][4];
#pragma unroll
            for (int mi = 0; mi < 2; mi++) {
                uint32_t ra = sb + offA + (uint32_t)(mi * 16 * SH * 2) + ko;
                ldm_x4(ah[mi], ra);
                ldm_x4(al[mi], ra + xl_off);
            }
#pragma unroll
            for (int nj = 0; nj < 2; nj++) {
                uint32_t rb = sb + offB + (uint32_t)(nj * 16 * SH * 2) + ko;
                ldm_x4(bh4[nj], rb + wh_off);
                ldm_x4(bl4[nj], rb + wl_off);
            }
#pragma unroll
            for (int ni = 0; ni < 4; ni++) {
                int nj = ni >> 1, sel = (ni & 1) * 2;
#pragma unroll
                for (int mi = 0; mi < 2; mi++)
                    mma_f16(C[mi * 4 + ni], ah[mi], bh4[nj][sel], bh4[nj][sel + 1]);
            }
#pragma unroll
            for (int ni = 0; ni < 4; ni++) {
                int nj = ni >> 1, sel = (ni & 1) * 2;
#pragma unroll
                for (int mi = 0; mi < 2; mi++)
                    mma_f16(C[mi * 4 + ni], ah[mi], bl4[nj][sel], bl4[nj][sel + 1]);
            }
#pragma unroll
            for (int ni = 0; ni < 4; ni++) {
                int nj = ni >> 1, sel = (ni & 1) * 2;
#pragma unroll
                for (int mi = 0; mi < 2; mi++)
                    mma_f16(C[mi * 4 + ni], al[mi], bh4[nj][sel], bh4[nj][sel + 1]);
            }
        }
    }

#pragma unroll
    for (int mi = 0; mi < 2; mi++) {
#pragma unroll
        for (int ni = 0; ni < 4; ni++) {
            const float* c = C[mi * 4 + ni];
            int col = nbase + (wn * 4 + ni) * 8 + 2 * tc;
            int h = col >> 6, d = col & 63;
            float b0 = bias[col], b1 = bias[col + 1];
#pragma unroll
            for (int half_ = 0; half_ < 2; half_++) {
                int r = mbase + (wm * 2 + mi) * 16 + gr + half_ * 8;
                int bb = r >> 11, l = r & 2047;
                size_t o = (((size_t)(bb * Hx + h)) * Lx + l) * DHx + d;
                float v0 = c[half_ * 2] + b0;
                float v1 = c[half_ * 2 + 1] + b1;
                *reinterpret_cast<float2*>(&out[o]) = make_float2(v0, v1);
                if (outHi) {
                    __half h0, l0, h1, l1;
                    split_h(v0, h0, l0);
                    split_h(v1, h1, l1);
                    *reinterpret_cast<__half2*>(&outHi[o]) = __halves2half2(h0, h1);
                    *reinterpret_cast<__half2*>(&outLo[o]) = __halves2half2(l0, l1);
                }
            }
        }
    }
}

// ---------------------------------------------------------------------------
// score_mma: rowmax(Q[128,64] @ K^T). 64 keys/stage, 3-stage cp.async,
// ldmatrix x4 A/B, pass-major MMA issue.
// ---------------------------------------------------------------------------
#define KSTAGE (2 * 64 * SH)
#define SCORE_SMEM ((2 * 128 * SH + 3 * KSTAGE) * 2 + 2 * 128 * 4)

__global__ __launch_bounds__(256, 2)
void score_mma_kernel()
{
    extern __shared__ __half smh[];
    __half* Qh = smh;
    __half* Ql = Qh + 128 * SH;
    __half* Kst = Ql + 128 * SH;
    float* red = reinterpret_cast<float*>(Kst + 3 * KSTAGE);

    const int tid = threadIdx.x;
    const int w = tid >> 5, lane = tid & 31;
    const int gr = lane >> 2, tc = lane & 3;
    const int wm = w >> 1, wn = w & 1;
    const int bh = blockIdx.y;
    const int qbase = blockIdx.x * 128;

    const uint32_t q_u32 = smem_u32(Qh);
    const uint32_t kst_u32 = smem_u32(Kst);

    auto prefetch_k = [&](int t, int stage) {
        const uint32_t sb = kst_u32 + (uint32_t)(stage * KSTAGE * 2);
#pragma unroll
        for (int i = 0; i < 4; i++) {
            int idx = tid + i * 256;
            int buf = idx >> 9;
            int within = idx & 511;
            int r = within >> 3;
            int u = (within & 7) * 8;
            uint32_t sa = sb + (uint32_t)((buf * 64 * SH + r * SH + u) * 2);
            const __half* gp = (buf == 0 ? g_Khi : g_Klo)
                               + ((size_t)bh * Lx + t * 64 + r) * DHx + u;
            cp16(sa, gp);
        }
        CP_COMMIT();
    };

#pragma unroll
    for (int i = 0; i < 4; i++) {
        int idx = tid + i * 256;
        int r = idx >> 3;
        int u = (idx & 7) * 8;
        size_t qs = ((size_t)bh * Lx + qbase + r) * DHx + u;
        *reinterpret_cast<uint4*>(Qh + r * SH + u) =
            *reinterpret_cast<const uint4*>(g_Qhi + qs);
        *reinterpret_cast<uint4*>(Ql + r * SH + u) =
            *reinterpret_cast<const uint4*>(g_Qlo + qs);
    }

    prefetch_k(0, 0);
    prefetch_k(1, 1);

    const uint32_t offA = (uint32_t)(((wm * 32 + (lane & 15)) * SH + (lane >> 4) * 8) * 2);
    const uint32_t offB = (uint32_t)(((wn * 32 + ((lane >> 4) & 1) * 8 + (lane & 7)) * SH
                                      + ((lane >> 3) & 1) * 8) * 2);
    const uint32_t ql_off = 128 * SH * 2;
    const uint32_t kl_off = 64 * SH * 2;

    float rm0[2], rm1[2];
#pragma unroll
    for (int mi = 0; mi < 2; mi++) { rm0[mi] = -1e30f; rm1[mi] = -1e30f; }

    for (int t = 0; t < 32; t++) {
        const int stage = t % 3;
        if (t < 31) CP_WAIT(1); else CP_WAIT(0);
        __syncthreads();
        if (t + 2 < 32) prefetch_k(t + 2, (t + 2) % 3);

        const uint32_t ksb = kst_u32 + (uint32_t)(stage * KSTAGE * 2);

        float C[8][4];
#pragma unroll
        for (int p = 0; p < 8; p++)
#pragma unroll
            for (int j = 0; j < 4; j++) C[p][j] = 0.f;

#pragma unroll
        for (int k16 = 0; k16 < 4; k16++) {
            const uint32_t ko = (uint32_t)(k16 * 16 * 2);
            uint32_t ah[2][4], al[2][4], bh4[2][4], bl4[2][4];
#pragma unroll
            for (int mi = 0; mi < 2; mi++) {
                uint32_t ra = q_u32 + offA + (uint32_t)(mi * 16 * SH * 2) + ko;
                ldm_x4(ah[mi], ra);
                ldm_x4(al[mi], ra + ql_off);
            }
#pragma unroll
            for (int nj = 0; nj < 2; nj++) {
                uint32_t rb = ksb + offB + (uint32_t)(nj * 16 * SH * 2) + ko;
                ldm_x4(bh4[nj], rb);
                ldm_x4(bl4[nj], rb + kl_off);
            }
#pragma unroll
            for (int ni = 0; ni < 4; ni++) {
                int nj = ni >> 1, sel = (ni & 1) * 2;
#pragma unroll
                for (int mi = 0; mi < 2; mi++)
                    mma_f16(C[mi * 4 + ni], ah[mi], bh4[nj][sel], bh4[nj][sel + 1]);
            }
#pragma unroll
            for (int ni = 0; ni < 4; ni++) {
                int nj = ni >> 1, sel = (ni & 1) * 2;
#pragma unroll
                for (int mi = 0; mi < 2; mi++)
                    mma_f16(C[mi * 4 + ni], ah[mi], bl4[nj][sel], bl4[nj][sel + 1]);
            }
#pragma unroll
            for (int ni = 0; ni < 4; ni++) {
                int nj = ni >> 1, sel = (ni & 1) * 2;
#pragma unroll
                for (int mi = 0; mi < 2; mi++)
                    mma_f16(C[mi * 4 + ni], al[mi], bh4[nj][sel], bh4[nj][sel + 1]);
            }
        }

#pragma unroll
        for (int mi = 0; mi < 2; mi++)
#pragma unroll
            for (int ni = 0; ni < 4; ni++) {
                const float* c = C[mi * 4 + ni];
                rm0[mi] = fmaxf(rm0[mi], fmaxf(c[0], c[1]));
                rm1[mi] = fmaxf(rm1[mi], fmaxf(c[2], c[3]));
            }
    }

#pragma unroll
    for (int mi = 0; mi < 2; mi++) {
        rm0[mi] = fmaxf(rm0[mi], __shfl_xor_sync(0xffffffffu, rm0[mi], 1));
        rm0[mi] = fmaxf(rm0[mi], __shfl_xor_sync(0xffffffffu, rm0[mi], 2));
        rm1[mi] = fmaxf(rm1[mi], __shfl_xor_sync(0xffffffffu, rm1[mi], 1));
        rm1[mi] = fmaxf(rm1[mi], __shfl_xor_sync(0xffffffffu, rm1[mi], 2));
    }
    __syncthreads();
    if (tc == 0) {
#pragma unroll
        for (int mi = 0; mi < 2; mi++) {
            int row = (wm * 2 + mi) * 16 + gr;
            red[wn * 128 + row] = rm0[mi];
            red[wn * 128 + row + 8] = rm1[mi];
        }
    }
    __syncthreads();
    if (tid < 128) {
        float m = fmaxf(red[tid], red[128 + tid]);
        g_rowmax[(size_t)bh * Lx + qbase + tid] = m;
    }
}

// ---------------------------------------------------------------------------
// K / V column sums (zeroed in prep_w).
// ---------------------------------------------------------------------------
__global__ void partial_sums_kernel()
{
    const int bh = blockIdx.x;
    const int kb = blockIdx.y * 128;
    const int tid = threadIdx.x;
    const int d = tid & 63, s = tid >> 6;
    float ks = 0.f, vs = 0.f;
    for (int k = kb + s; k < kb + 128; k += 4) {
        ks += g_K[((size_t)bh * Lx + k) * DHx + d];
        vs += g_V[((size_t)bh * Lx + k) * DHx + d];
    }
    __shared__ float red[2][256];
    red[0][tid] = ks;
    red[1][tid] = vs;
    __syncthreads();
    if (tid < 64) {
        float a = red[0][d] + red[0][d + 64] + red[0][d + 128] + red[0][d + 192];
        float b = red[1][d] + red[1][d + 64] + red[1][d + 128] + red[1][d + 192];
        atomicAdd(&g_Ksum[bh * DHx + d], a);
        atomicAdd(&g_Vsum[bh * DHx + d], b);
    }
}

// ---------------------------------------------------------------------------
// M = SCALE * (rowmax - Q.Ksum / L)
// ---------------------------------------------------------------------------
__global__ void mstat_kernel()
{
    int gidx = blockIdx.x * 256 + threadIdx.x;
    int bh = gidx >> 11;
    const float* qp = g_Q + (size_t)gidx * DHx;
    const float* ks = g_Ksum + bh * DHx;
    float dot = 0.f;
#pragma unroll
    for (int d = 0; d < DHx; d += 4) {
        float4 a = *reinterpret_cast<const float4*>(qp + d);
        float4 b = *reinterpret_cast<const float4*>(ks + d);
        dot += a.x * b.x + a.y * b.y + a.z * b.z + a.w * b.w;
    }
    g_M[gidx] = SCALEF * (g_rowmax[gidx] - dot * (1.0f / Lx));
}

// ---------------------------------------------------------------------------
// Top-38 per bh: packed (value, ~index) uint64 keys, shfl-reduce.
// ---------------------------------------------------------------------------
__global__ void topk_kernel()
{
    const int bh = blockIdx.x;
    const int tid = threadIdx.x;
    const int lane = tid & 31, warp = tid >> 5;
    __shared__ float vals[Lx];
    __shared__ unsigned long long wred[8];

    for (int i = tid; i < Lx; i += 256) vals[i] = g_M[(size_t)bh * Lx + i];
    __syncthreads();

    for (int it = 0; it < KTOP; it++) {
        unsigned long long best = 0ull;
#pragma unroll
        for (int j = 0; j < Lx / 256; j++) {
            int i = tid + j * 256;
            uint32_t fb = __float_as_uint(vals[i]);
            fb = (fb & 0x80000000u) ? ~fb : (fb | 0x80000000u);
            unsigned long long key =
                ((unsigned long long)fb << 32) | (uint32_t)(~i);
            if (key > best) best = key;
        }
#pragma unroll
        for (int o = 16; o > 0; o >>= 1) {
            unsigned long long other = __shfl_xor_sync(0xffffffffu, best, o);
            if (other > best) best = other;
        }
        if (lane == 0) wred[warp] = best;
        __syncthreads();
        if (tid == 0) {
            unsigned long long b = wred[0];
#pragma unroll
            for (int v = 1; v < 8; v++) if (wred[v] > b) b = wred[v];
            int idx = (int)(~(uint32_t)b);
            g_top[bh * KTOP + it] = idx;
            vals[idx] = -1e30f;
        }
        __syncthreads();
    }
}

// ---------------------------------------------------------------------------
// Sparse attention, 8 queries per block, quarter-warp QK, warp-per-query
// softmax (exact fp32).
// ---------------------------------------------------------------------------
#define SPARSE_SMEM ((8 * Lx + 8 * DHx + 8 + 8 * 256) * 4)

__global__ __launch_bounds__(256)
void sparse_attn_kernel()
{
    extern __shared__ float sm[];
    float (*sc)[Lx]   = reinterpret_cast<float(*)[Lx]>(sm);
    float (*qrow)[DHx] = reinterpret_cast<float(*)[DHx]>(sm + 8 * Lx);
    float* invs = sm + 8 * Lx + 8 * DHx;
    float (*red2)[256] = reinterpret_cast<float(*)[256]>(invs + 8);

    const int bh = blockIdx.y;
    const int tid = threadIdx.x;
    const int warp = tid >> 5, lane = tid & 31;
    const int qq = lane >> 3;
    const int l8 = lane & 7;

    for (int e = tid; e < 8 * DHx; e += 256) {
        int s = e >> 6, d = e & 63;
        int i = blockIdx.x + NQB * s;
        qrow[s][d] = (i < KTOP)
            ? g_Q[((size_t)bh * Lx + g_top[bh * KTOP + i]) * DHx + d] : 0.f;
    }
    __syncthreads();

    float4 qf[8][2];
#pragma unroll
    for (int s = 0; s < 8; s++) {
        qf[s][0] = *reinterpret_cast<const float4*>(&qrow[s][l8 * 8]);
        qf[s][1] = *reinterpret_cast<const float4*>(&qrow[s][l8 * 8 + 4]);
    }

    for (int it = 0; it < Lx / 32; it++) {
        int k = it * 32 + warp * 4 + qq;
        const float* kr = g_K + ((size_t)bh * Lx + k) * DHx;
        float4 a = *reinterpret_cast<const float4*>(kr + l8 * 8);
        float4 b = *reinterpret_cast<const float4*>(kr + l8 * 8 + 4);
        float dts[8];
#pragma unroll
        for (int s = 0; s < 8; s++) {
            dts[s] = a.x*qf[s][0].x + a.y*qf[s][0].y + a.z*qf[s][0].z + a.w*qf[s][0].w
                   + b.x*qf[s][1].x + b.y*qf[s][1].y + b.z*qf[s][1].z + b.w*qf[s][1].w;
        }
#pragma unroll
        for (int o = 4; o > 0; o >>= 1)
#pragma unroll
            for (int s = 0; s < 8; s++)
                dts[s] += __shfl_xor_sync(0xffffffffu, dts[s], o);
        if (l8 == 0) {
#pragma unroll
            for (int s = 0; s < 8; s++) sc[s][k] = dts[s] * SCALEF;
        }
    }
    __syncthreads();

    {
        float* scp = sc[warp];
        float mx = -1e30f;
        for (int k = lane; k < Lx; k += 32) mx = fmaxf(mx, scp[k]);
#pragma unroll
        for (int o = 16; o > 0; o >>= 1)
            mx = fmaxf(mx, __shfl_xor_sync(0xffffffffu, mx, o));
        float sum = 0.f;
        for (int k = lane; k < Lx; k += 32) {
            float e = __expf(scp[k] - mx);
            scp[k] = e;
            sum += e;
        }
#pragma unroll
        for (int o = 16; o > 0; o >>= 1)
            sum += __shfl_xor_sync(0xffffffffu, sum, o);
        if (lane == 0) invs[warp] = 1.0f / sum;
    }
    __syncthreads();

    const int d = tid & 63, s4 = tid >> 6;
    float acc[8] = {0.f, 0.f, 0.f, 0.f, 0.f, 0.f, 0.f, 0.f};
    for (int k = s4; k < Lx; k += 4) {
        float v = g_V[((size_t)bh * Lx + k) * DHx + d];
#pragma unroll
        for (int s = 0; s < 8; s++) acc[s] += sc[s][k] * v;
    }
#pragma unroll
    for (int s = 0; s < 8; s++) red2[s][tid] = acc[s];
    __syncthreads();
    if (tid < 64) {
        float vm = g_Vsum[bh * DHx + d] * (1.0f / Lx);
#pragma unroll
        for (int s = 0; s < 8; s++) {
            int i = blockIdx.x + NQB * s;
            if (i >= KTOP) continue;
            float c = (red2[s][d] + red2[s][d + 64] + red2[s][d + 128] + red2[s][d + 192])
                      * invs[s];
            g_delta[((size_t)bh * KTOP + i) * DHx + d] = c - vm;
        }
    }
}

// ---------------------------------------------------------------------------
__global__ void base_kernel(const float* __restrict__ Wo, const float* __restrict__ bo)
{
    int b = blockIdx.x, j = threadIdx.x;
    float acc = bo[j];
    for (int c = 0; c < Dx; c++) {
        int h = c >> 6, d = c & 63;
        acc += g_Vsum[(b * Hx + h) * DHx + d] * (1.0f / Lx) * Wo[(size_t)c * Dx + j];
    }
    g_base[b * Dx + j] = acc;
}

__global__ void fill_kernel(float* __restrict__ out)
{
    size_t i4 = (size_t)blockIdx.x * 256 + threadIdx.x;
    int b = (int)(i4 >> 18);
    int j4 = (int)(i4 & (Dx / 4 - 1));
    *reinterpret_cast<float4*>(out + i4 * 4) =
        *reinterpret_cast<const float4*>(g_base + b * Dx + j4 * 4);
}

__global__ void scatter_kernel(const float* __restrict__ Wo, float* __restrict__ out)
{
    const int bh = blockIdx.y;
    const int i = blockIdx.x;
    const int j = threadIdx.x;
    const int b = bh >> 3, h = bh & 7;
    const int l = g_top[bh * KTOP + i];
    __shared__ float dl[DHx];
    if (j < 64) dl[j] = g_delta[((size_t)bh * KTOP + i) * DHx + j];
    __syncthreads();
    float acc = 0.f;
#pragma unroll 16
    for (int d = 0; d < 64; d++) acc += dl[d] * Wo[(size_t)(h * 64 + d) * Dx + j];
    atomicAdd(&out[((size_t)b * Lx + l) * Dx + j], acc);
}

// ---------------------------------------------------------------------------
extern "C" void kernel_launch(void* const* d_in, const int* in_sizes, int n_in,
                              void* d_out, int out_size)
{
    const float* x  = (const float*)d_in[0];
    const float* Wq = (const float*)d_in[1];
    const float* bq = (const float*)d_in[2];
    const float* Wk = (const float*)d_in[3];
    const float* bk = (const float*)d_in[4];
    const float* Wv = (const float*)d_in[5];
    const float* bv = (const float*)d_in[6];
    const float* Wo = (const float*)d_in[7];
    const float* bo = (const float*)d_in[8];
    float* out = (float*)d_out;

    (void)in_sizes; (void)n_in; (void)out_size;

    cudaFuncSetAttribute(proj_mma_kernel,
                         cudaFuncAttributeMaxDynamicSharedMemorySize, PROJ_SMEM);
    cudaFuncSetAttribute(score_mma_kernel,
                         cudaFuncAttributeMaxDynamicSharedMemorySize, SCORE_SMEM);
    cudaFuncSetAttribute(sparse_attn_kernel,
                         cudaFuncAttributeMaxDynamicSharedMemorySize, SPARSE_SMEM);

    const int x4half = (Bx * Lx * Dx / 4) / 2;   // half the float4 count

    prep_w_kernel<<<dim3(16, 16, 3), 256>>>(Wq, Wk, Wv);          // 0 (+ zero sums)
    prep_x_kernel<<<x4half / 256, 256>>>(x, 0);                   // 1
    prep_x_kernel<<<x4half / 256, 256>>>(x, x4half);              // 2

    dim3 pg(Dx / 64, (Bx * Lx) / 128, 3);   // (8, 64, 3)
    proj_mma_kernel<<<pg, 256, PROJ_SMEM>>>(bq, bk, bv);          // 3 <- ncu target

    score_mma_kernel<<<dim3(Lx / 128, BHx), 256, SCORE_SMEM>>>(); // 4
    partial_sums_kernel<<<dim3(BHx, 16), 256>>>();                // 5
    mstat_kernel<<<BHx * Lx / 256, 256>>>();                      // 6
    topk_kernel<<<BHx, 256>>>();                                  // 7
    sparse_attn_kernel<<<dim3(NQB, BHx), 256, SPARSE_SMEM>>>();   // 8
    base_kernel<<<Bx, Dx>>>(Wo, bo);                              // 9
    fill_kernel<<<(Bx * Lx * Dx / 4) / 256, 256>>>(out);          // 10
    scatter_kernel<<<dim3(KTOP, BHx), Dx>>>(Wo, out);             // 11
}